// round 1
// baseline (speedup 1.0000x reference)
#include <cuda_runtime.h>

#define BB 32
#define SS 256
#define EE 256
#define HH 8
#define DKK 32
#define LL 4
#define TT (BB*SS)
#define E3 (3*EE)

// ---------------- scratch (static device arrays; no allocation) ----------------
__device__ float g_x[TT*EE];
__device__ float g_q[TT*EE];
__device__ float g_k[TT*EE];
__device__ float g_v[TT*EE];
__device__ float g_heads[TT*EE];
__device__ float g_hcat[TT*E3];
__device__ float g_h[TT*EE];
__device__ float g_h2[TT*EE];
__device__ float g_wq[12*EE*EE];
__device__ float g_wk[12*EE*EE];
__device__ float g_wv[12*EE*EE];
__device__ int   g_flag[TT];
__device__ int   g_len[BB];
__device__ float g_part[2*256*EE];
__device__ float g_mean[EE];
__device__ float g_rstd[EE];

// ---------------- weight packing: (lg,H,E,DK) -> (lg,E,H*DK) ----------------
__global__ void pack_w(const float* __restrict__ Wq, const float* __restrict__ Wk,
                       const float* __restrict__ Wv) {
    int id = blockIdx.x*blockDim.x + threadIdx.x;   // 0 .. 12*H*E*DK-1
    int d  = id % DKK;
    int e  = (id / DKK) % EE;
    int h  = (id / (DKK*EE)) % HH;
    int lg = id / (DKK*EE*HH);
    int dst = (lg*EE + e)*EE + h*DKK + d;
    g_wq[dst] = Wq[id];
    g_wk[dst] = Wk[id];
    g_wv[dst] = Wv[id];
}

// ---------------- flags + lengths ----------------
__global__ void flags_kernel(const float* __restrict__ data, const float* __restrict__ mask) {
    int b = blockIdx.x, s = threadIdx.x;
    int idx = b*SS + s;
    float mk = mask[idx];
    float p1 = data[idx*5+2], p2 = data[idx*5+3], p3 = data[idx*5+4];
    int f = 0;
    if (p1 == 1.0f) f = 100;
    if (p2 == 1.0f || p3 == 1.0f) f = 101;
    if (mk == 0.0f) f = 102;
    g_flag[idx] = f;
    __shared__ float red[SS];
    red[s] = mk;
    __syncthreads();
    for (int st = 128; st > 0; st >>= 1) {
        if (s < st) red[s] += red[s+st];
        __syncthreads();
    }
    if (s == 0) g_len[b] = (int)(red[0] + 0.5f);
}

// ---------------- input embedding ----------------
__global__ void embed_kernel(const float* __restrict__ data, const float* __restrict__ Wc,
                             const float* __restrict__ bc, const float* __restrict__ ftab,
                             const float* __restrict__ ptab) {
    int t = blockIdx.x;
    int e = threadIdx.x;
    float c0 = data[t*5+0], c1 = data[t*5+1];
    int fl = g_flag[t];
    int s = t & (SS-1);
    g_x[t*EE+e] = c0*Wc[e] + c1*Wc[EE+e] + bc[e] + ftab[fl*EE+e] + ptab[s*EE+e];
}

// ---------------- generic tiled SGEMM 64x64x16, 256 threads, 4x4 per thread -----
// C[m,n] = sum_k A[m,k]*B[k,n]  (+bias[n])  (relu)  (+resid[m,n])
__global__ void __launch_bounds__(256) sgemm_kernel(
    const float* __restrict__ A, const float* __restrict__ Bm, float* __restrict__ C,
    int K, int lda, int ldb, int ldc,
    const float* __restrict__ bias, const float* __restrict__ resid, int ldr, int relu)
{
    __shared__ float sA[16][64];
    __shared__ float sB[16][64];
    int tid = threadIdx.x;
    int tx = tid & 15, ty = tid >> 4;
    int m0 = blockIdx.y*64, n0 = blockIdx.x*64;
    float acc[4][4] = {};
    int arow = tid >> 2, aseg = tid & 3;
    int brow = tid >> 4, bseg = tid & 15;
    for (int k0 = 0; k0 < K; k0 += 16) {
        float4 av = *(const float4*)&A[(size_t)(m0+arow)*lda + k0 + aseg*4];
        sA[aseg*4+0][arow] = av.x;
        sA[aseg*4+1][arow] = av.y;
        sA[aseg*4+2][arow] = av.z;
        sA[aseg*4+3][arow] = av.w;
        *(float4*)&sB[brow][bseg*4] = *(const float4*)&Bm[(size_t)(k0+brow)*ldb + n0 + bseg*4];
        __syncthreads();
#pragma unroll
        for (int kk = 0; kk < 16; kk++) {
            float4 a = *(const float4*)&sA[kk][ty*4];
            float4 b = *(const float4*)&sB[kk][tx*4];
            float aa[4] = {a.x,a.y,a.z,a.w};
            float bb[4] = {b.x,b.y,b.z,b.w};
#pragma unroll
            for (int i = 0; i < 4; i++)
#pragma unroll
                for (int j = 0; j < 4; j++)
                    acc[i][j] += aa[i]*bb[j];
        }
        __syncthreads();
    }
#pragma unroll
    for (int i = 0; i < 4; i++) {
        int row = m0 + ty*4 + i;
#pragma unroll
        for (int j = 0; j < 4; j++) {
            int col = n0 + tx*4 + j;
            float v2 = acc[i][j];
            if (bias)  v2 += bias[col];
            if (relu)  v2 = fmaxf(v2, 0.0f);
            if (resid) v2 += resid[(size_t)row*ldr + col];
            C[(size_t)row*ldc + col] = v2;
        }
    }
}

// ---------------- adjacency predicate (masks computed on the fly) --------------
__device__ __forceinline__ bool adj_fn(int g, int q, int k, int len, const int* fl) {
    if (q == k) return q < len;
    if (g == 0) {
        if (k == q+1) return fl[q] == 100 && q < len-1;
        if (q == k+1) return fl[k] == 100 && k < len-1;
        return false;
    } else if (g == 1) {
        if (k == q+1) return fl[q] == 100 && q < len-1;
        if (q == k+1) return fl[k] == 100 && k < len-1;
        if (k == q+2) return fl[q] == 100 && fl[q+1] == 100 && q < len-2;
        if (q == k+2) return fl[k] == 100 && fl[k+1] == 100 && k < len-2;
        return false;
    } else {
        if (q == 0 && k == len-1 && len > 1) return true;
        if (k == 0 && q == len-1 && len > 1) return true;
        if (k == q+1) return fl[q] == 101 && q < len-1;
        if (q == k+1) return fl[k] == 101 && k < len-1;
        return false;
    }
}

// ---------------- fused attention: one thread per query row, online softmax ----
__global__ void __launch_bounds__(256) attn_kernel(
    const float* __restrict__ q, const float* __restrict__ k,
    const float* __restrict__ v, float* __restrict__ outp, int g)
{
    __shared__ int   sFlag[SS];
    __shared__ float sK[64][32];
    __shared__ float sV[64][32];
    __shared__ int   sLen;
    int b = blockIdx.x, h = blockIdx.y;
    int qi = threadIdx.x;
    sFlag[qi] = g_flag[b*SS + qi];
    if (qi == 0) sLen = g_len[b];
    __syncthreads();
    int t = b*SS + qi;
    float qr[32];
#pragma unroll
    for (int d = 0; d < 32; d++) qr[d] = q[(size_t)t*EE + h*32 + d];
    int len = sLen;
    int fq_base = b*SS;
    (void)fq_base;
    float m = -1e30f, ssum = 0.0f;
    float o[32];
#pragma unroll
    for (int d = 0; d < 32; d++) o[d] = 0.0f;
    const float scale = 0.17677669529663687f;
    int r = threadIdx.x >> 2, sg = threadIdx.x & 3;
    for (int c = 0; c < 4; c++) {
        __syncthreads();
        const float* kp = k + (size_t)(b*SS + c*64 + r)*EE + h*32 + sg*8;
        const float* vp = v + (size_t)(b*SS + c*64 + r)*EE + h*32 + sg*8;
        *(float4*)&sK[r][sg*8]   = *(const float4*)kp;
        *(float4*)&sK[r][sg*8+4] = *(const float4*)(kp+4);
        *(float4*)&sV[r][sg*8]   = *(const float4*)vp;
        *(float4*)&sV[r][sg*8+4] = *(const float4*)(vp+4);
        __syncthreads();
        for (int j = 0; j < 64; j++) {
            int kidx = c*64 + j;
            bool adj = adj_fn(g, qi, kidx, len, sFlag);
            // once an unmasked key has been seen (m > -1e9), masked keys are exact zeros
            if (!adj && m > -1e9f) continue;
            float dot = 0.0f;
#pragma unroll
            for (int d = 0; d < 32; d++) dot += qr[d]*sK[j][d];
            float logit = dot*scale + (adj ? 0.0f : -1e10f);
            if (logit <= m) {
                float p = __expf(logit - m);
                if (p > 0.0f) {
                    ssum += p;
#pragma unroll
                    for (int d = 0; d < 32; d++) o[d] += p*sV[j][d];
                }
            } else {
                float corr = __expf(m - logit);
                ssum = ssum*corr + 1.0f;
#pragma unroll
                for (int d = 0; d < 32; d++) o[d] = o[d]*corr + sV[j][d];
                m = logit;
            }
        }
    }
    float inv = 1.0f / ssum;
#pragma unroll
    for (int d = 0; d < 32; d++) outp[(size_t)t*EE + h*32 + d] = o[d]*inv;
}

// ---------------- batchnorm over (B,S) per feature ----------------
__global__ void bn_part_kernel(const float* __restrict__ x) {
    int c = blockIdx.x, f = threadIdx.x;
    float s = 0.0f, s2 = 0.0f;
    for (int t = c*32; t < c*32 + 32; t++) {
        float val = x[(size_t)t*EE + f];
        s  += val;
        s2 += val*val;
    }
    g_part[c*EE + f] = s;
    g_part[256*EE + c*EE + f] = s2;
}

__global__ void bn_stats_kernel() {
    int f = threadIdx.x;
    double s = 0.0, s2 = 0.0;
    for (int j = 0; j < 256; j++) {
        s  += (double)g_part[j*EE + f];
        s2 += (double)g_part[256*EE + j*EE + f];
    }
    float mean = (float)(s / (double)TT);
    float var  = (float)(s2 / (double)TT) - mean*mean;
    g_mean[f] = mean;
    g_rstd[f] = rsqrtf(var + 1e-5f);
}

__global__ void bn_norm_kernel(const float* __restrict__ in, float* __restrict__ outp,
                               const float* __restrict__ gamma, const float* __restrict__ beta) {
    int t = blockIdx.x, f = threadIdx.x;
    outp[(size_t)t*EE + f] = gamma[f]*(in[(size_t)t*EE + f] - g_mean[f])*g_rstd[f] + beta[f];
}

// ---------------- masked mean over S ----------------
__global__ void final_kernel(const float* __restrict__ mask, float* __restrict__ outp) {
    __shared__ float sM[SS];
    int b = blockIdx.x, e = threadIdx.x;
    sM[e] = mask[b*SS + e];
    __syncthreads();
    float acc = 0.0f;
    for (int s = 0; s < SS; s++) acc += g_x[(size_t)(b*SS + s)*EE + e]*sM[s];
    float denom = fmaxf((float)g_len[b], 1.0f);
    outp[b*EE + e] = acc/denom;
}

// ---------------- host orchestration (graph-capturable) ----------------
extern "C" void kernel_launch(void* const* d_in, const int* in_sizes, int n_in,
                              void* d_out, int out_size) {
    (void)in_sizes; (void)n_in; (void)out_size;
    const float* data = (const float*)d_in[0];
    const float* mask = (const float*)d_in[1];
    const float* Wc   = (const float*)d_in[2];
    const float* bc   = (const float*)d_in[3];
    const float* ftab = (const float*)d_in[4];
    const float* ptab = (const float*)d_in[5];
    const float* Wq   = (const float*)d_in[6];
    const float* Wk   = (const float*)d_in[7];
    const float* Wv   = (const float*)d_in[8];
    const float* Wo   = (const float*)d_in[9];
    const float* Wf   = (const float*)d_in[10];
    const float* bf   = (const float*)d_in[11];
    const float* g1   = (const float*)d_in[12];
    const float* b1   = (const float*)d_in[13];
    const float* Wff  = (const float*)d_in[14];
    const float* bff  = (const float*)d_in[15];
    const float* g2   = (const float*)d_in[16];
    const float* b2   = (const float*)d_in[17];
    float* outp = (float*)d_out;

    float *x, *q, *k, *v, *heads, *hcat, *h, *h2, *wq, *wk, *wv;
    cudaGetSymbolAddress((void**)&x,     g_x);
    cudaGetSymbolAddress((void**)&q,     g_q);
    cudaGetSymbolAddress((void**)&k,     g_k);
    cudaGetSymbolAddress((void**)&v,     g_v);
    cudaGetSymbolAddress((void**)&heads, g_heads);
    cudaGetSymbolAddress((void**)&hcat,  g_hcat);
    cudaGetSymbolAddress((void**)&h,     g_h);
    cudaGetSymbolAddress((void**)&h2,    g_h2);
    cudaGetSymbolAddress((void**)&wq,    g_wq);
    cudaGetSymbolAddress((void**)&wk,    g_wk);
    cudaGetSymbolAddress((void**)&wv,    g_wv);

    pack_w<<<(12*HH*EE*DKK)/256, 256>>>(Wq, Wk, Wv);
    flags_kernel<<<BB, SS>>>(data, mask);
    embed_kernel<<<TT, EE>>>(data, Wc, bc, ftab, ptab);

    dim3 gemmGrid(EE/64, TT/64);   // (4, 128)
    for (int l = 0; l < LL; l++) {
        for (int g = 0; g < 3; g++) {
            int lg = l*3 + g;
            sgemm_kernel<<<gemmGrid, 256>>>(x, wq + (size_t)lg*EE*EE, q,
                                            EE, EE, EE, EE, nullptr, nullptr, 0, 0);
            sgemm_kernel<<<gemmGrid, 256>>>(x, wk + (size_t)lg*EE*EE, k,
                                            EE, EE, EE, EE, nullptr, nullptr, 0, 0);
            sgemm_kernel<<<gemmGrid, 256>>>(x, wv + (size_t)lg*EE*EE, v,
                                            EE, EE, EE, EE, nullptr, nullptr, 0, 0);
            attn_kernel<<<dim3(BB, HH), 256>>>(q, k, v, heads, g);
            // hcat[:, g*E : (g+1)*E] = x + heads @ Wo[l,g]   (Wo block is (H*DK, E) row-major)
            sgemm_kernel<<<gemmGrid, 256>>>(heads, Wo + (size_t)lg*EE*EE, hcat + g*EE,
                                            EE, EE, EE, E3, nullptr, x, EE, 0);
        }
        // h = hcat @ Wf[l] + bf[l]
        sgemm_kernel<<<gemmGrid, 256>>>(hcat, Wf + (size_t)l*E3*EE, h,
                                        E3, E3, EE, EE, bf + l*EE, nullptr, 0, 0);
        bn_part_kernel<<<256, 256>>>(h);
        bn_stats_kernel<<<1, 256>>>();
        bn_norm_kernel<<<TT, EE>>>(h, h, g1 + l*EE, b1 + l*EE);
        // h2 = h + relu(h @ Wff[l] + bff[l])
        sgemm_kernel<<<gemmGrid, 256>>>(h, Wff + (size_t)l*EE*EE, h2,
                                        EE, EE, EE, EE, bff + l*EE, h, EE, 1);
        bn_part_kernel<<<256, 256>>>(h2);
        bn_stats_kernel<<<1, 256>>>();
        bn_norm_kernel<<<TT, EE>>>(h2, x, g2 + l*EE, b2 + l*EE);
    }
    final_kernel<<<BB, EE>>>(mask, outp);
}

// round 2
// speedup vs baseline: 2.5273x; 2.5273x over previous
#include <cuda_runtime.h>

#define BB 32
#define SS 256
#define EE 256
#define HH 8
#define DKK 32
#define LL 4
#define TT (BB*SS)
#define E3 (3*EE)
#define QKVW 2304   // 3 groups * (q|k|v) * 256

// ---------------- scratch (static device arrays; no allocation) ----------------
__device__ float g_x[TT*EE];
__device__ float g_qkv[TT*QKVW];
__device__ float g_heads[3*TT*EE];
__device__ float g_hcat[TT*E3];
__device__ float g_h[TT*EE];
__device__ float g_h2[TT*EE];
__device__ float g_wqkv[LL*EE*QKVW];
__device__ int   g_flag[TT];
__device__ int   g_len[BB];
__device__ float g_part[2*128*EE];
__device__ float g_mean[EE];
__device__ float g_rstd[EE];

// ---------------- weight packing: (l,g,H,E,DK) -> (l, E, g*768 + {q,k,v}*256 + h*32 + d)
__global__ void pack_w(const float* __restrict__ Wq, const float* __restrict__ Wk,
                       const float* __restrict__ Wv) {
    int id = blockIdx.x*blockDim.x + threadIdx.x;   // 0 .. 12*H*E*DK-1
    int d  = id % DKK;
    int e  = (id / DKK) % EE;
    int h  = (id / (DKK*EE)) % HH;
    int lg = id / (DKK*EE*HH);
    int l = lg / 3, g = lg % 3;
    size_t dst = ((size_t)l*EE + e)*QKVW + g*768 + h*DKK + d;
    g_wqkv[dst +   0] = Wq[id];
    g_wqkv[dst + 256] = Wk[id];
    g_wqkv[dst + 512] = Wv[id];
}

// ---------------- flags + lengths ----------------
__global__ void flags_kernel(const float* __restrict__ data, const float* __restrict__ mask) {
    int b = blockIdx.x, s = threadIdx.x;
    int idx = b*SS + s;
    float mk = mask[idx];
    float p1 = data[idx*5+2], p2 = data[idx*5+3], p3 = data[idx*5+4];
    int f = 0;
    if (p1 == 1.0f) f = 100;
    if (p2 == 1.0f || p3 == 1.0f) f = 101;
    if (mk == 0.0f) f = 102;
    g_flag[idx] = f;
    __shared__ float red[SS];
    red[s] = mk;
    __syncthreads();
    for (int st = 128; st > 0; st >>= 1) {
        if (s < st) red[s] += red[s+st];
        __syncthreads();
    }
    if (s == 0) g_len[b] = (int)(red[0] + 0.5f);
}

// ---------------- input embedding ----------------
__global__ void embed_kernel(const float* __restrict__ data, const float* __restrict__ Wc,
                             const float* __restrict__ bc, const float* __restrict__ ftab,
                             const float* __restrict__ ptab) {
    int t = blockIdx.x;
    int e = threadIdx.x;
    float c0 = data[t*5+0], c1 = data[t*5+1];
    int fl = g_flag[t];
    int s = t & (SS-1);
    g_x[t*EE+e] = c0*Wc[e] + c1*Wc[EE+e] + bc[e] + ftab[fl*EE+e] + ptab[s*EE+e];
}

// ---------------- tf32 tensor-core GEMM ----------------
// C[m,n] = sum_k A[m,k]*B[k,n]  (+bias[n]) (relu) (+resid[m,n]) ; optional z batching
__device__ __forceinline__ unsigned f2tf(float x) {
    unsigned r; asm("cvt.rna.tf32.f32 %0, %1;" : "=r"(r) : "f"(x)); return r;
}

#define SA_STRIDE 36
#define SB_STRIDE 136

__global__ void __launch_bounds__(256, 2) mma_gemm(
    const float* __restrict__ A, const float* __restrict__ Bm, float* __restrict__ C,
    int K, int lda, int ldb, int ldc,
    const float* __restrict__ bias, const float* __restrict__ resid, int ldr, int relu,
    size_t batchA, size_t batchB, size_t batchC)
{
    __shared__ unsigned sA[128*SA_STRIDE];
    __shared__ unsigned sB[32*SB_STRIDE];
    int z = blockIdx.z;
    A  += (size_t)z*batchA;
    Bm += (size_t)z*batchB;
    C  += (size_t)z*batchC;
    int tid = threadIdx.x, lane = tid & 31, warp = tid >> 5;
    int wm = warp & 1, wn = warp >> 1;       // warp tile: 64 (M) x 32 (N)
    int m0 = blockIdx.y*128, n0 = blockIdx.x*128;
    float acc[4][4][4];
#pragma unroll
    for (int a2 = 0; a2 < 4; a2++)
#pragma unroll
        for (int b2 = 0; b2 < 4; b2++)
#pragma unroll
            for (int c2 = 0; c2 < 4; c2++) acc[a2][b2][c2] = 0.0f;

    int a_r = tid >> 1, a_c = (tid & 1)*16;   // A tile 128x32
    int b_r = tid >> 3, b_c = (tid & 7)*16;   // B tile 32x128
    const float* Aptr = A + (size_t)(m0 + a_r)*lda + a_c;
    const float* Bbase = Bm + n0 + b_c;

    for (int k0 = 0; k0 < K; k0 += 32) {
#pragma unroll
        for (int j = 0; j < 4; j++) {
            float4 av = *(const float4*)(Aptr + k0 + j*4);
            sA[a_r*SA_STRIDE + a_c + j*4 + 0] = f2tf(av.x);
            sA[a_r*SA_STRIDE + a_c + j*4 + 1] = f2tf(av.y);
            sA[a_r*SA_STRIDE + a_c + j*4 + 2] = f2tf(av.z);
            sA[a_r*SA_STRIDE + a_c + j*4 + 3] = f2tf(av.w);
        }
        const float* Bp = Bbase + (size_t)(k0 + b_r)*ldb;
#pragma unroll
        for (int j = 0; j < 4; j++) {
            float4 bv = *(const float4*)(Bp + j*4);
            sB[b_r*SB_STRIDE + b_c + j*4 + 0] = f2tf(bv.x);
            sB[b_r*SB_STRIDE + b_c + j*4 + 1] = f2tf(bv.y);
            sB[b_r*SB_STRIDE + b_c + j*4 + 2] = f2tf(bv.z);
            sB[b_r*SB_STRIDE + b_c + j*4 + 3] = f2tf(bv.w);
        }
        __syncthreads();
#pragma unroll
        for (int kk = 0; kk < 4; kk++) {
            int kb = kk*8;
            unsigned af[4][4], bf[4][2];
#pragma unroll
            for (int mt = 0; mt < 4; mt++) {
                int r = wm*64 + mt*16 + (lane >> 2);
                int kc = kb + (lane & 3);
                af[mt][0] = sA[r*SA_STRIDE + kc];
                af[mt][1] = sA[(r+8)*SA_STRIDE + kc];
                af[mt][2] = sA[r*SA_STRIDE + kc + 4];
                af[mt][3] = sA[(r+8)*SA_STRIDE + kc + 4];
            }
#pragma unroll
            for (int nt = 0; nt < 4; nt++) {
                int c = wn*32 + nt*8 + (lane >> 2);
                int kr = kb + (lane & 3);
                bf[nt][0] = sB[kr*SB_STRIDE + c];
                bf[nt][1] = sB[(kr+4)*SB_STRIDE + c];
            }
#pragma unroll
            for (int mt = 0; mt < 4; mt++)
#pragma unroll
                for (int nt = 0; nt < 4; nt++)
                    asm volatile(
                        "mma.sync.aligned.m16n8k8.row.col.f32.tf32.tf32.f32 "
                        "{%0,%1,%2,%3}, {%4,%5,%6,%7}, {%8,%9}, {%0,%1,%2,%3};"
                        : "+f"(acc[mt][nt][0]), "+f"(acc[mt][nt][1]),
                          "+f"(acc[mt][nt][2]), "+f"(acc[mt][nt][3])
                        : "r"(af[mt][0]), "r"(af[mt][1]), "r"(af[mt][2]), "r"(af[mt][3]),
                          "r"(bf[nt][0]), "r"(bf[nt][1]));
        }
        __syncthreads();
    }
    // epilogue
#pragma unroll
    for (int mt = 0; mt < 4; mt++) {
#pragma unroll
        for (int nt = 0; nt < 4; nt++) {
            int r = m0 + wm*64 + mt*16 + (lane >> 2);
            int c = n0 + wn*32 + nt*8 + (lane & 3)*2;
#pragma unroll
            for (int half = 0; half < 2; half++) {
                int rr = r + half*8;
                float v0 = acc[mt][nt][half*2+0];
                float v1 = acc[mt][nt][half*2+1];
                if (bias)  { v0 += bias[c];  v1 += bias[c+1]; }
                if (relu)  { v0 = fmaxf(v0, 0.0f); v1 = fmaxf(v1, 0.0f); }
                if (resid) { v0 += resid[(size_t)rr*ldr + c]; v1 += resid[(size_t)rr*ldr + c+1]; }
                C[(size_t)rr*ldc + c]   = v0;
                C[(size_t)rr*ldc + c+1] = v1;
            }
        }
    }
}

// ---------------- adjacency predicate ----------------
__device__ __forceinline__ bool adj_fn(int g, int q, int k, int len, const int* fl) {
    if (q == k) return q < len;
    if (g == 0) {
        if (k == q+1) return fl[q] == 100 && q < len-1;
        if (q == k+1) return fl[k] == 100 && k < len-1;
        return false;
    } else if (g == 1) {
        if (k == q+1) return fl[q] == 100 && q < len-1;
        if (q == k+1) return fl[k] == 100 && k < len-1;
        if (k == q+2) return fl[q] == 100 && fl[q+1] == 100 && q < len-2;
        if (q == k+2) return fl[k] == 100 && fl[k+1] == 100 && k < len-2;
        return false;
    } else {
        if (q == 0 && k == len-1 && len > 1) return true;
        if (k == 0 && q == len-1 && len > 1) return true;
        if (k == q+1) return fl[q] == 101 && q < len-1;
        if (q == k+1) return fl[k] == 101 && k < len-1;
        return false;
    }
}

// ---------------- sparse attention: <=7 candidate keys per valid query ----------
// pad queries (q >= len): all 256 logits are exactly -1e10 in fp32 -> uniform -> mean(V)
__global__ void __launch_bounds__(256) attn_kernel(
    const float* __restrict__ qkv, float* __restrict__ heads, int g)
{
    __shared__ float sPart[8][32];
    __shared__ float sVmean[32];
    __shared__ int   sFlag[SS];
    __shared__ int   sLenS;
    int b = blockIdx.x, h = blockIdx.y;
    int tid = threadIdx.x;
    const float* basep = qkv + (size_t)b*SS*QKVW + g*768 + h*DKK;
    // mean of V over all 256 rows (for pad queries)
    {
        int d = tid & 31, chunk = tid >> 5;
        float s = 0.0f;
        for (int r = chunk*32; r < chunk*32 + 32; r++)
            s += basep[(size_t)r*QKVW + 512 + d];
        sPart[chunk][d] = s;
    }
    sFlag[tid] = g_flag[b*SS + tid];
    if (tid == 0) sLenS = g_len[b];
    __syncthreads();
    if (tid < 32) {
        float s = 0.0f;
#pragma unroll
        for (int c2 = 0; c2 < 8; c2++) s += sPart[c2][tid];
        sVmean[tid] = s * (1.0f/256.0f);
    }
    __syncthreads();
    int qi = tid, len = sLenS;
    float* op = heads + ((size_t)g*TT + b*SS + qi)*EE + h*DKK;
    if (qi >= len) {
#pragma unroll
        for (int j = 0; j < 8; j++)
            *(float4*)(op + j*4) = *(float4*)(&sVmean[j*4]);
        return;
    }
    // load q row
    float qr[32];
    const float* qp = basep + (size_t)qi*QKVW;
#pragma unroll
    for (int j = 0; j < 8; j++) {
        float4 t4 = *(const float4*)(qp + j*4);
        qr[j*4+0] = t4.x; qr[j*4+1] = t4.y; qr[j*4+2] = t4.z; qr[j*4+3] = t4.w;
    }
    // candidate keys (ascending, unique)
    int cand[8]; int nc = 0;
    int pot[7];  int np = 0;
    if (g == 2) pot[np++] = 0;
    pot[np++] = qi-2; pot[np++] = qi-1; pot[np++] = qi; pot[np++] = qi+1; pot[np++] = qi+2;
    if (g == 2) pot[np++] = len-1;
    for (int i = 0; i < np; i++) {
        int kk = pot[i];
        if (kk < 0 || kk >= SS) continue;
        if (!adj_fn(g, qi, kk, len, sFlag)) continue;
        bool dup = false;
        for (int u = 0; u < nc; u++) if (cand[u] == kk) dup = true;
        if (!dup) cand[nc++] = kk;
    }
    const float scale = 0.17677669529663687f;
    float lg[8];
    float m = -1e30f;
    for (int i = 0; i < nc; i++) {
        const float* kp = basep + (size_t)cand[i]*QKVW + 256;
        float dot = 0.0f;
#pragma unroll
        for (int j = 0; j < 8; j++) {
            float4 k4 = *(const float4*)(kp + j*4);
            dot += qr[j*4+0]*k4.x + qr[j*4+1]*k4.y + qr[j*4+2]*k4.z + qr[j*4+3]*k4.w;
        }
        lg[i] = dot * scale;
        m = fmaxf(m, lg[i]);
    }
    float ssum = 0.0f;
    float o[32];
#pragma unroll
    for (int d = 0; d < 32; d++) o[d] = 0.0f;
    for (int i = 0; i < nc; i++) {
        float p = expf(lg[i] - m);
        ssum += p;
        const float* vp = basep + (size_t)cand[i]*QKVW + 512;
#pragma unroll
        for (int j = 0; j < 8; j++) {
            float4 v4 = *(const float4*)(vp + j*4);
            o[j*4+0] += p*v4.x; o[j*4+1] += p*v4.y; o[j*4+2] += p*v4.z; o[j*4+3] += p*v4.w;
        }
    }
    float inv = 1.0f / ssum;
#pragma unroll
    for (int j = 0; j < 8; j++) {
        float4 w4 = make_float4(o[j*4+0]*inv, o[j*4+1]*inv, o[j*4+2]*inv, o[j*4+3]*inv);
        *(float4*)(op + j*4) = w4;
    }
}

// ---------------- batchnorm over (B,S) per feature ----------------
__global__ void bn_part_kernel(const float* __restrict__ x) {
    int c = blockIdx.x, f = threadIdx.x;   // 128 chunks x 64 rows
    float s = 0.0f, s2 = 0.0f;
    for (int t = c*64; t < c*64 + 64; t++) {
        float val = x[(size_t)t*EE + f];
        s  += val;
        s2 += val*val;
    }
    g_part[c*EE + f] = s;
    g_part[128*EE + c*EE + f] = s2;
}

__global__ void bn_stats_kernel() {
    int f = blockIdx.x, t = threadIdx.x;   // one block (32 thr) per feature
    double s = 0.0, s2 = 0.0;
    for (int j = t; j < 128; j += 32) {
        s  += (double)g_part[j*EE + f];
        s2 += (double)g_part[128*EE + j*EE + f];
    }
#pragma unroll
    for (int o = 16; o > 0; o >>= 1) {
        s  += __shfl_down_sync(0xffffffffu, s,  o);
        s2 += __shfl_down_sync(0xffffffffu, s2, o);
    }
    if (t == 0) {
        float mean = (float)(s / (double)TT);
        float var  = (float)(s2 / (double)TT) - mean*mean;
        g_mean[f] = mean;
        g_rstd[f] = rsqrtf(var + 1e-5f);
    }
}

__global__ void bn_norm_kernel(const float* __restrict__ in, float* __restrict__ outp,
                               const float* __restrict__ gamma, const float* __restrict__ beta) {
    int t = blockIdx.x, f = threadIdx.x;
    outp[(size_t)t*EE + f] = gamma[f]*(in[(size_t)t*EE + f] - g_mean[f])*g_rstd[f] + beta[f];
}

// ---------------- masked mean over S ----------------
__global__ void final_kernel(const float* __restrict__ mask, float* __restrict__ outp) {
    __shared__ float sM[SS];
    int b = blockIdx.x, e = threadIdx.x;
    sM[e] = mask[b*SS + e];
    __syncthreads();
    float acc = 0.0f;
    for (int s = 0; s < SS; s++) acc += g_x[(size_t)(b*SS + s)*EE + e]*sM[s];
    float denom = fmaxf((float)g_len[b], 1.0f);
    outp[b*EE + e] = acc/denom;
}

// ---------------- host orchestration (graph-capturable) ----------------
extern "C" void kernel_launch(void* const* d_in, const int* in_sizes, int n_in,
                              void* d_out, int out_size) {
    (void)in_sizes; (void)n_in; (void)out_size;
    const float* data = (const float*)d_in[0];
    const float* mask = (const float*)d_in[1];
    const float* Wc   = (const float*)d_in[2];
    const float* bc   = (const float*)d_in[3];
    const float* ftab = (const float*)d_in[4];
    const float* ptab = (const float*)d_in[5];
    const float* Wq   = (const float*)d_in[6];
    const float* Wk   = (const float*)d_in[7];
    const float* Wv   = (const float*)d_in[8];
    const float* Wo   = (const float*)d_in[9];
    const float* Wf   = (const float*)d_in[10];
    const float* bf   = (const float*)d_in[11];
    const float* g1   = (const float*)d_in[12];
    const float* b1   = (const float*)d_in[13];
    const float* Wff  = (const float*)d_in[14];
    const float* bff  = (const float*)d_in[15];
    const float* g2   = (const float*)d_in[16];
    const float* b2   = (const float*)d_in[17];
    float* outp = (float*)d_out;

    float *x, *qkv, *heads, *hcat, *h, *h2, *wqkv;
    cudaGetSymbolAddress((void**)&x,     g_x);
    cudaGetSymbolAddress((void**)&qkv,   g_qkv);
    cudaGetSymbolAddress((void**)&heads, g_heads);
    cudaGetSymbolAddress((void**)&hcat,  g_hcat);
    cudaGetSymbolAddress((void**)&h,     g_h);
    cudaGetSymbolAddress((void**)&h2,    g_h2);
    cudaGetSymbolAddress((void**)&wqkv,  g_wqkv);

    pack_w<<<(12*HH*EE*DKK)/256, 256>>>(Wq, Wk, Wv);
    flags_kernel<<<BB, SS>>>(data, mask);
    embed_kernel<<<TT, EE>>>(data, Wc, bc, ftab, ptab);

    for (int l = 0; l < LL; l++) {
        // qkv (all 3 groups): (TT,256) @ (256,2304)
        mma_gemm<<<dim3(QKVW/128, TT/128, 1), 256>>>(
            x, wqkv + (size_t)l*EE*QKVW, qkv,
            EE, EE, QKVW, QKVW, nullptr, nullptr, 0, 0, 0, 0, 0);
        for (int g = 0; g < 3; g++)
            attn_kernel<<<dim3(BB, HH), 256>>>(qkv, heads, g);
        // hcat[:, g*E:(g+1)*E] = x + heads_g @ Wo[l,g]   (z-batched over g)
        mma_gemm<<<dim3(EE/128, TT/128, 3), 256>>>(
            heads, Wo + (size_t)l*3*EE*EE, hcat,
            EE, EE, EE, E3, nullptr, x, EE, 0,
            (size_t)TT*EE, (size_t)EE*EE, (size_t)EE);
        // h = hcat @ Wf[l] + bf[l]
        mma_gemm<<<dim3(EE/128, TT/128, 1), 256>>>(
            hcat, Wf + (size_t)l*E3*EE, h,
            E3, E3, EE, EE, bf + l*EE, nullptr, 0, 0, 0, 0, 0);
        bn_part_kernel<<<128, 256>>>(h);
        bn_stats_kernel<<<EE, 32>>>();
        bn_norm_kernel<<<TT, EE>>>(h, h, g1 + l*EE, b1 + l*EE);
        // h2 = h + relu(h @ Wff[l] + bff[l])
        mma_gemm<<<dim3(EE/128, TT/128, 1), 256>>>(
            h, Wff + (size_t)l*EE*EE, h2,
            EE, EE, EE, EE, bff + l*EE, h, EE, 1, 0, 0, 0);
        bn_part_kernel<<<128, 256>>>(h2);
        bn_stats_kernel<<<EE, 32>>>();
        bn_norm_kernel<<<TT, EE>>>(h2, x, g2 + l*EE, b2 + l*EE);
    }
    final_kernel<<<BB, EE>>>(mask, outp);
}

// round 5
// speedup vs baseline: 4.1523x; 1.6430x over previous
#include <cuda_runtime.h>

#define BB 32
#define SS 256
#define EE 256
#define HH 8
#define DKK 32
#define LL 4
#define TT (BB*SS)
#define E3 (3*EE)
#define QKVW 2304   // 3 groups * (q|k|v) * 256

// ---------------- scratch (static device arrays; no allocation) ----------------
__device__ float g_x[TT*EE];
__device__ float g_qkv[TT*QKVW];
__device__ float g_heads[3*TT*EE];
__device__ float g_hcat[TT*E3];
__device__ float g_h[TT*EE];
__device__ float g_h2[TT*EE];
__device__ float g_wqkv[LL*EE*QKVW];
__device__ int   g_flag[TT];
__device__ int   g_len[BB];
__device__ float g_part[2*128*EE];
__device__ float g_mean[EE];
__device__ float g_rstd[EE];

// ---------------- weight packing: (l,g,H,E,DK) -> (l, E, g*768 + {q,k,v}*256 + h*32 + d)
__global__ void pack_w(const float* __restrict__ Wq, const float* __restrict__ Wk,
                       const float* __restrict__ Wv) {
    int id = blockIdx.x*blockDim.x + threadIdx.x;   // 0 .. 12*H*E*DK-1
    int d  = id % DKK;
    int e  = (id / DKK) % EE;
    int h  = (id / (DKK*EE)) % HH;
    int lg = id / (DKK*EE*HH);
    int l = lg / 3, g = lg % 3;
    size_t dst = ((size_t)l*EE + e)*QKVW + g*768 + h*DKK + d;
    g_wqkv[dst +   0] = Wq[id];
    g_wqkv[dst + 256] = Wk[id];
    g_wqkv[dst + 512] = Wv[id];
}

// ---------------- flags + lengths ----------------
__global__ void flags_kernel(const float* __restrict__ data, const float* __restrict__ mask) {
    int b = blockIdx.x, s = threadIdx.x;
    int idx = b*SS + s;
    float mk = mask[idx];
    float p1 = data[idx*5+2], p2 = data[idx*5+3], p3 = data[idx*5+4];
    int f = 0;
    if (p1 == 1.0f) f = 100;
    if (p2 == 1.0f || p3 == 1.0f) f = 101;
    if (mk == 0.0f) f = 102;
    g_flag[idx] = f;
    __shared__ float red[SS];
    red[s] = mk;
    __syncthreads();
    for (int st = 128; st > 0; st >>= 1) {
        if (s < st) red[s] += red[s+st];
        __syncthreads();
    }
    if (s == 0) g_len[b] = (int)(red[0] + 0.5f);
}

// ---------------- input embedding ----------------
__global__ void embed_kernel(const float* __restrict__ data, const float* __restrict__ Wc,
                             const float* __restrict__ bc, const float* __restrict__ ftab,
                             const float* __restrict__ ptab) {
    int t = blockIdx.x;
    int e = threadIdx.x;
    float c0 = data[t*5+0], c1 = data[t*5+1];
    int fl = g_flag[t];
    int s = t & (SS-1);
    g_x[t*EE+e] = c0*Wc[e] + c1*Wc[EE+e] + bc[e] + ftab[fl*EE+e] + ptab[s*EE+e];
}

// ---------------- tf32 tensor-core GEMM with cp.async double buffering --------
__device__ __forceinline__ unsigned f2tf(float x) {
    unsigned r; asm("cvt.rna.tf32.f32 %0, %1;" : "=r"(r) : "f"(x)); return r;
}
__device__ __forceinline__ void cpasync16(float* dst, const float* src) {
    unsigned s = (unsigned)__cvta_generic_to_shared(dst);
    asm volatile("cp.async.cg.shared.global [%0], [%1], 16;" :: "r"(s), "l"(src));
}

#define SA_ST 36
#define SB_ST 136
#define TILE_A_W (128*SA_ST)        // 4608 words
#define TILE_B_W (32*SB_ST)         // 4352 words
#define BUF_W (TILE_A_W + TILE_B_W) // 8960 words
#define GEMM_SMEM (2*BUF_W*4)       // 71680 bytes

__device__ __forceinline__ void load_tile(float* bufA, float* bufB,
        const float* A, const float* Bm, int lda, int ldb,
        int m0, int n0, int k0, int tid)
{
    // A tile: 128 rows x 32 k; each thread: 16 consecutive floats of one row (4x16B)
    {
        int row = tid >> 1, c = (tid & 1)*16;
        const float* src = A + (size_t)(m0 + row)*lda + k0 + c;
        float* dst = bufA + row*SA_ST + c;
        cpasync16(dst,      src);
        cpasync16(dst + 4,  src + 4);
        cpasync16(dst + 8,  src + 8);
        cpasync16(dst + 12, src + 12);
    }
    // B tile: 32 k x 128 cols; each thread: 16 consecutive floats of one k-row (4x16B)
    {
        int krow = tid >> 3, c = (tid & 7)*16;
        const float* src = Bm + (size_t)(k0 + krow)*ldb + n0 + c;
        float* dst = bufB + krow*SB_ST + c;
        cpasync16(dst,      src);
        cpasync16(dst + 4,  src + 4);
        cpasync16(dst + 8,  src + 8);
        cpasync16(dst + 12, src + 12);
    }
    asm volatile("cp.async.commit_group;");
}

__global__ void __launch_bounds__(256, 2) mma_gemm(
    const float* __restrict__ A, const float* __restrict__ Bm, float* __restrict__ C,
    int K, int lda, int ldb, int ldc,
    const float* __restrict__ bias, const float* __restrict__ resid, int ldr, int relu,
    size_t batchA, size_t batchB, size_t batchC)
{
    extern __shared__ float smem[];
    int z = blockIdx.z;
    A  += (size_t)z*batchA;
    Bm += (size_t)z*batchB;
    C  += (size_t)z*batchC;
    int tid = threadIdx.x, lane = tid & 31, warp = tid >> 5;
    int wm = warp & 1, wn = warp >> 1;       // warp tile: 64 (M) x 32 (N)
    int m0 = blockIdx.y*128, n0 = blockIdx.x*128;
    float acc[4][4][4];
#pragma unroll
    for (int a2 = 0; a2 < 4; a2++)
#pragma unroll
        for (int b2 = 0; b2 < 4; b2++)
#pragma unroll
            for (int c2 = 0; c2 < 4; c2++) acc[a2][b2][c2] = 0.0f;

    int nk = K >> 5;
    load_tile(smem, smem + TILE_A_W, A, Bm, lda, ldb, m0, n0, 0, tid);

    for (int it = 0; it < nk; it++) {
        asm volatile("cp.async.wait_group 0;");
        __syncthreads();
        int cur = it & 1;
        if (it + 1 < nk)
            load_tile(smem + (cur^1)*BUF_W, smem + (cur^1)*BUF_W + TILE_A_W,
                      A, Bm, lda, ldb, m0, n0, (it+1)*32, tid);
        const float* sA = smem + cur*BUF_W;
        const float* sB = sA + TILE_A_W;
#pragma unroll
        for (int kk = 0; kk < 4; kk++) {
            int kb = kk*8;
            unsigned af[4][4], bf[4][2];
#pragma unroll
            for (int mt = 0; mt < 4; mt++) {
                int r = wm*64 + mt*16 + (lane >> 2);
                int kc = kb + (lane & 3);
                af[mt][0] = f2tf(sA[r*SA_ST + kc]);
                af[mt][1] = f2tf(sA[(r+8)*SA_ST + kc]);
                af[mt][2] = f2tf(sA[r*SA_ST + kc + 4]);
                af[mt][3] = f2tf(sA[(r+8)*SA_ST + kc + 4]);
            }
#pragma unroll
            for (int nt = 0; nt < 4; nt++) {
                int c = wn*32 + nt*8 + (lane >> 2);
                int kr = kb + (lane & 3);
                bf[nt][0] = f2tf(sB[kr*SB_ST + c]);
                bf[nt][1] = f2tf(sB[(kr+4)*SB_ST + c]);
            }
#pragma unroll
            for (int mt = 0; mt < 4; mt++)
#pragma unroll
                for (int nt = 0; nt < 4; nt++)
                    asm volatile(
                        "mma.sync.aligned.m16n8k8.row.col.f32.tf32.tf32.f32 "
                        "{%0,%1,%2,%3}, {%4,%5,%6,%7}, {%8,%9}, {%0,%1,%2,%3};"
                        : "+f"(acc[mt][nt][0]), "+f"(acc[mt][nt][1]),
                          "+f"(acc[mt][nt][2]), "+f"(acc[mt][nt][3])
                        : "r"(af[mt][0]), "r"(af[mt][1]), "r"(af[mt][2]), "r"(af[mt][3]),
                          "r"(bf[nt][0]), "r"(bf[nt][1]));
        }
        __syncthreads();
    }
    // epilogue
#pragma unroll
    for (int mt = 0; mt < 4; mt++) {
#pragma unroll
        for (int nt = 0; nt < 4; nt++) {
            int r = m0 + wm*64 + mt*16 + (lane >> 2);
            int c = n0 + wn*32 + nt*8 + (lane & 3)*2;
#pragma unroll
            for (int half = 0; half < 2; half++) {
                int rr = r + half*8;
                float v0 = acc[mt][nt][half*2+0];
                float v1 = acc[mt][nt][half*2+1];
                if (bias)  { v0 += bias[c];  v1 += bias[c+1]; }
                if (relu)  { v0 = fmaxf(v0, 0.0f); v1 = fmaxf(v1, 0.0f); }
                if (resid) { v0 += resid[(size_t)rr*ldr + c]; v1 += resid[(size_t)rr*ldr + c+1]; }
                C[(size_t)rr*ldc + c]   = v0;
                C[(size_t)rr*ldc + c+1] = v1;
            }
        }
    }
}

// ---------------- adjacency predicate ----------------
__device__ __forceinline__ bool adj_fn(int g, int q, int k, int len, const int* fl) {
    if (q == k) return q < len;
    if (g == 0) {
        if (k == q+1) return fl[q] == 100 && q < len-1;
        if (q == k+1) return fl[k] == 100 && k < len-1;
        return false;
    } else if (g == 1) {
        if (k == q+1) return fl[q] == 100 && q < len-1;
        if (q == k+1) return fl[k] == 100 && k < len-1;
        if (k == q+2) return fl[q] == 100 && fl[q+1] == 100 && q < len-2;
        if (q == k+2) return fl[k] == 100 && fl[k+1] == 100 && k < len-2;
        return false;
    } else {
        if (q == 0 && k == len-1 && len > 1) return true;
        if (k == 0 && q == len-1 && len > 1) return true;
        if (k == q+1) return fl[q] == 101 && q < len-1;
        if (q == k+1) return fl[k] == 101 && k < len-1;
        return false;
    }
}

// ---------------- sparse attention: <=7 candidate keys per valid query ----------
__global__ void __launch_bounds__(256) attn_kernel(
    const float* __restrict__ qkv, float* __restrict__ heads)
{
    __shared__ float sPart[8][32];
    __shared__ float sVmean[32];
    __shared__ int   sFlag[SS];
    __shared__ int   sLenS;
    int b = blockIdx.x, h = blockIdx.y, g = blockIdx.z;
    int tid = threadIdx.x;
    const float* basep = qkv + (size_t)b*SS*QKVW + g*768 + h*DKK;
    // mean of V over all 256 rows (for pad queries)
    {
        int d = tid & 31, chunk = tid >> 5;
        float s = 0.0f;
        for (int r = chunk*32; r < chunk*32 + 32; r++)
            s += basep[(size_t)r*QKVW + 512 + d];
        sPart[chunk][d] = s;
    }
    sFlag[tid] = g_flag[b*SS + tid];
    if (tid == 0) sLenS = g_len[b];
    __syncthreads();
    if (tid < 32) {
        float s = 0.0f;
#pragma unroll
        for (int c2 = 0; c2 < 8; c2++) s += sPart[c2][tid];
        sVmean[tid] = s * (1.0f/256.0f);
    }
    __syncthreads();
    int qi = tid, len = sLenS;
    float* op = heads + ((size_t)g*TT + b*SS + qi)*EE + h*DKK;
    if (qi >= len) {
#pragma unroll
        for (int j = 0; j < 8; j++)
            *(float4*)(op + j*4) = *(float4*)(&sVmean[j*4]);
        return;
    }
    float qr[32];
    const float* qp = basep + (size_t)qi*QKVW;
#pragma unroll
    for (int j = 0; j < 8; j++) {
        float4 t4 = *(const float4*)(qp + j*4);
        qr[j*4+0] = t4.x; qr[j*4+1] = t4.y; qr[j*4+2] = t4.z; qr[j*4+3] = t4.w;
    }
    int cand[8]; int nc = 0;
    int pot[7];  int np = 0;
    if (g == 2) pot[np++] = 0;
    pot[np++] = qi-2; pot[np++] = qi-1; pot[np++] = qi; pot[np++] = qi+1; pot[np++] = qi+2;
    if (g == 2) pot[np++] = len-1;
    for (int i = 0; i < np; i++) {
        int kk = pot[i];
        if (kk < 0 || kk >= SS) continue;
        if (!adj_fn(g, qi, kk, len, sFlag)) continue;
        bool dup = false;
        for (int u = 0; u < nc; u++) if (cand[u] == kk) dup = true;
        if (!dup) cand[nc++] = kk;
    }
    const float scale = 0.17677669529663687f;
    float lg[8];
    float m = -1e30f;
    for (int i = 0; i < nc; i++) {
        const float* kp = basep + (size_t)cand[i]*QKVW + 256;
        float dot = 0.0f;
#pragma unroll
        for (int j = 0; j < 8; j++) {
            float4 k4 = *(const float4*)(kp + j*4);
            dot += qr[j*4+0]*k4.x + qr[j*4+1]*k4.y + qr[j*4+2]*k4.z + qr[j*4+3]*k4.w;
        }
        lg[i] = dot * scale;
        m = fmaxf(m, lg[i]);
    }
    float ssum = 0.0f;
    float o[32];
#pragma unroll
    for (int d = 0; d < 32; d++) o[d] = 0.0f;
    for (int i = 0; i < nc; i++) {
        float p = expf(lg[i] - m);
        ssum += p;
        const float* vp = basep + (size_t)cand[i]*QKVW + 512;
#pragma unroll
        for (int j = 0; j < 8; j++) {
            float4 v4 = *(const float4*)(vp + j*4);
            o[j*4+0] += p*v4.x; o[j*4+1] += p*v4.y; o[j*4+2] += p*v4.z; o[j*4+3] += p*v4.w;
        }
    }
    float inv = 1.0f / ssum;
#pragma unroll
    for (int j = 0; j < 8; j++) {
        float4 w4 = make_float4(o[j*4+0]*inv, o[j*4+1]*inv, o[j*4+2]*inv, o[j*4+3]*inv);
        *(float4*)(op + j*4) = w4;
    }
}

// ---------------- batchnorm over (B,S) per feature ----------------
__global__ void bn_part_kernel(const float* __restrict__ x) {
    int c = blockIdx.x, f = threadIdx.x;   // 128 chunks x 64 rows
    float s = 0.0f, s2 = 0.0f;
    for (int t = c*64; t < c*64 + 64; t++) {
        float val = x[(size_t)t*EE + f];
        s  += val;
        s2 += val*val;
    }
    g_part[c*EE + f] = s;
    g_part[128*EE + c*EE + f] = s2;
}

__global__ void bn_stats_kernel() {
    int f = blockIdx.x, t = threadIdx.x;
    double s = 0.0, s2 = 0.0;
    for (int j = t; j < 128; j += 32) {
        s  += (double)g_part[j*EE + f];
        s2 += (double)g_part[128*EE + j*EE + f];
    }
#pragma unroll
    for (int o = 16; o > 0; o >>= 1) {
        s  += __shfl_down_sync(0xffffffffu, s,  o);
        s2 += __shfl_down_sync(0xffffffffu, s2, o);
    }
    if (t == 0) {
        float mean = (float)(s / (double)TT);
        float var  = (float)(s2 / (double)TT) - mean*mean;
        g_mean[f] = mean;
        g_rstd[f] = rsqrtf(var + 1e-5f);
    }
}

__global__ void bn_norm_kernel(const float* __restrict__ in, float* __restrict__ outp,
                               const float* __restrict__ gamma, const float* __restrict__ beta) {
    int t = blockIdx.x, f = threadIdx.x;
    outp[(size_t)t*EE + f] = gamma[f]*(in[(size_t)t*EE + f] - g_mean[f])*g_rstd[f] + beta[f];
}

// ---------------- masked mean over S ----------------
__global__ void final_kernel(const float* __restrict__ mask, float* __restrict__ outp) {
    __shared__ float sM[SS];
    int b = blockIdx.x, e = threadIdx.x;
    sM[e] = mask[b*SS + e];
    __syncthreads();
    float acc = 0.0f;
    for (int s = 0; s < SS; s++) acc += g_x[(size_t)(b*SS + s)*EE + e]*sM[s];
    float denom = fmaxf((float)g_len[b], 1.0f);
    outp[b*EE + e] = acc/denom;
}

// ---------------- host orchestration (graph-capturable) ----------------
extern "C" void kernel_launch(void* const* d_in, const int* in_sizes, int n_in,
                              void* d_out, int out_size) {
    (void)in_sizes; (void)n_in; (void)out_size;
    const float* data = (const float*)d_in[0];
    const float* mask = (const float*)d_in[1];
    const float* Wc   = (const float*)d_in[2];
    const float* bc   = (const float*)d_in[3];
    const float* ftab = (const float*)d_in[4];
    const float* ptab = (const float*)d_in[5];
    const float* Wq   = (const float*)d_in[6];
    const float* Wk   = (const float*)d_in[7];
    const float* Wv   = (const float*)d_in[8];
    const float* Wo   = (const float*)d_in[9];
    const float* Wf   = (const float*)d_in[10];
    const float* bf   = (const float*)d_in[11];
    const float* g1   = (const float*)d_in[12];
    const float* b1   = (const float*)d_in[13];
    const float* Wff  = (const float*)d_in[14];
    const float* bff  = (const float*)d_in[15];
    const float* g2   = (const float*)d_in[16];
    const float* b2   = (const float*)d_in[17];
    float* outp = (float*)d_out;

    float *x, *qkv, *heads, *hcat, *h, *h2, *wqkv;
    cudaGetSymbolAddress((void**)&x,     g_x);
    cudaGetSymbolAddress((void**)&qkv,   g_qkv);
    cudaGetSymbolAddress((void**)&heads, g_heads);
    cudaGetSymbolAddress((void**)&hcat,  g_hcat);
    cudaGetSymbolAddress((void**)&h,     g_h);
    cudaGetSymbolAddress((void**)&h2,    g_h2);
    cudaGetSymbolAddress((void**)&wqkv,  g_wqkv);

    cudaFuncSetAttribute(mma_gemm, cudaFuncAttributeMaxDynamicSharedMemorySize, GEMM_SMEM);

    pack_w<<<(12*HH*EE*DKK)/256, 256>>>(Wq, Wk, Wv);
    flags_kernel<<<BB, SS>>>(data, mask);
    embed_kernel<<<TT, EE>>>(data, Wc, bc, ftab, ptab);

    for (int l = 0; l < LL; l++) {
        // qkv (all 3 groups): (TT,256) @ (256,2304)
        mma_gemm<<<dim3(QKVW/128, TT/128, 1), 256, GEMM_SMEM>>>(
            x, wqkv + (size_t)l*EE*QKVW, qkv,
            EE, EE, QKVW, QKVW, nullptr, nullptr, 0, 0, 0, 0, 0);
        attn_kernel<<<dim3(BB, HH, 3), 256>>>(qkv, heads);
        // hcat[:, g*E:(g+1)*E] = x + heads_g @ Wo[l,g]   (z-batched over g)
        mma_gemm<<<dim3(EE/128, TT/128, 3), 256, GEMM_SMEM>>>(
            heads, Wo + (size_t)l*3*EE*EE, hcat,
            EE, EE, EE, E3, nullptr, x, EE, 0,
            (size_t)TT*EE, (size_t)EE*EE, (size_t)EE);
        // h = hcat @ Wf[l] + bf[l]
        mma_gemm<<<dim3(EE/128, TT/128, 1), 256, GEMM_SMEM>>>(
            hcat, Wf + (size_t)l*E3*EE, h,
            E3, E3, EE, EE, bf + l*EE, nullptr, 0, 0, 0, 0, 0);
        bn_part_kernel<<<128, 256>>>(h);
        bn_stats_kernel<<<EE, 32>>>();
        bn_norm_kernel<<<TT, EE>>>(h, h, g1 + l*EE, b1 + l*EE);
        // h2 = h + relu(h @ Wff[l] + bff[l])
        mma_gemm<<<dim3(EE/128, TT/128, 1), 256, GEMM_SMEM>>>(
            h, Wff + (size_t)l*EE*EE, h2,
            EE, EE, EE, EE, bff + l*EE, h, EE, 1, 0, 0, 0);
        bn_part_kernel<<<128, 256>>>(h2);
        bn_stats_kernel<<<EE, 32>>>();
        bn_norm_kernel<<<TT, EE>>>(h2, x, g2 + l*EE, b2 + l*EE);
    }
    final_kernel<<<BB, EE>>>(mask, outp);
}

// round 6
// speedup vs baseline: 4.5232x; 1.0893x over previous
#include <cuda_runtime.h>

#define BB 32
#define SS 256
#define EE 256
#define HH 8
#define DKK 32
#define LL 4
#define TT (BB*SS)
#define E3 (3*EE)
#define QKVW 2304   // 3 groups * (q|k|v) * 256

// ---------------- scratch (static device arrays; no allocation) ----------------
__device__ float g_x[TT*EE];
__device__ float g_qkv[TT*QKVW];
__device__ float g_heads[3*TT*EE];
__device__ float g_hcat[TT*E3];
__device__ float g_h[TT*EE];
__device__ float g_h2[TT*EE];
__device__ float g_wqkv[LL*EE*QKVW];
__device__ float g_wo[12*EE*EE];
__device__ float g_wf[LL*E3*EE];
__device__ float g_wff[LL*EE*EE];
__device__ int   g_flag[TT];
__device__ int   g_len[BB];
__device__ float g_sums[2*EE];
__device__ float g_mean[EE];
__device__ float g_rstd[EE];

__device__ __forceinline__ unsigned f2tf(float x) {
    unsigned r; asm("cvt.rna.tf32.f32 %0, %1;" : "=r"(r) : "f"(x)); return r;
}

// ---------------- weight packing: (l,g,H,E,DK) -> (l, E, g*768 + {q,k,v}*256 + h*32 + d)
// stored pre-rounded to tf32
__global__ void pack_w(const float* __restrict__ Wq, const float* __restrict__ Wk,
                       const float* __restrict__ Wv) {
    int id = blockIdx.x*blockDim.x + threadIdx.x;   // 0 .. 12*H*E*DK-1
    int d  = id % DKK;
    int e  = (id / DKK) % EE;
    int h  = (id / (DKK*EE)) % HH;
    int lg = id / (DKK*EE*HH);
    int l = lg / 3, g = lg % 3;
    size_t dst = ((size_t)l*EE + e)*QKVW + g*768 + h*DKK + d;
    g_wqkv[dst +   0] = __uint_as_float(f2tf(Wq[id]));
    g_wqkv[dst + 256] = __uint_as_float(f2tf(Wk[id]));
    g_wqkv[dst + 512] = __uint_as_float(f2tf(Wv[id]));
}

__global__ void round_copy(const float* __restrict__ src, float* __restrict__ dst, int n) {
    int i = blockIdx.x*blockDim.x + threadIdx.x;
    if (i < n) dst[i] = __uint_as_float(f2tf(src[i]));
}

// ---------------- flags + lengths ----------------
__global__ void flags_kernel(const float* __restrict__ data, const float* __restrict__ mask) {
    int b = blockIdx.x, s = threadIdx.x;
    int idx = b*SS + s;
    float mk = mask[idx];
    float p1 = data[idx*5+2], p2 = data[idx*5+3], p3 = data[idx*5+4];
    int f = 0;
    if (p1 == 1.0f) f = 100;
    if (p2 == 1.0f || p3 == 1.0f) f = 101;
    if (mk == 0.0f) f = 102;
    g_flag[idx] = f;
    __shared__ float red[SS];
    red[s] = mk;
    __syncthreads();
    for (int st = 128; st > 0; st >>= 1) {
        if (s < st) red[s] += red[s+st];
        __syncthreads();
    }
    if (s == 0) g_len[b] = (int)(red[0] + 0.5f);
}

// ---------------- input embedding ----------------
__global__ void embed_kernel(const float* __restrict__ data, const float* __restrict__ Wc,
                             const float* __restrict__ bc, const float* __restrict__ ftab,
                             const float* __restrict__ ptab) {
    int t = blockIdx.x;
    int e = threadIdx.x;
    float c0 = data[t*5+0], c1 = data[t*5+1];
    int fl = g_flag[t];
    int s = t & (SS-1);
    g_x[t*EE+e] = c0*Wc[e] + c1*Wc[EE+e] + bc[e] + ftab[fl*EE+e] + ptab[s*EE+e];
}

// ---------------- tf32 tensor-core GEMM with cp.async double buffering --------
__device__ __forceinline__ void cpasync16(float* dst, const float* src) {
    unsigned s = (unsigned)__cvta_generic_to_shared(dst);
    asm volatile("cp.async.cg.shared.global [%0], [%1], 16;" :: "r"(s), "l"(src));
}

#define SA_ST 36
#define SB_ST 136
#define TILE_A_W (128*SA_ST)        // 4608 words
#define TILE_B_W (32*SB_ST)         // 4352 words
#define BUF_W (TILE_A_W + TILE_B_W) // 8960 words
#define GEMM_SMEM (2*BUF_W*4)       // 71680 bytes

__device__ __forceinline__ void load_tile(float* bufA, float* bufB,
        const float* A, const float* Bm, int lda, int ldb,
        int m0, int n0, int k0, int tid)
{
    {
        int row = tid >> 1, c = (tid & 1)*16;
        const float* src = A + (size_t)(m0 + row)*lda + k0 + c;
        float* dst = bufA + row*SA_ST + c;
        cpasync16(dst,      src);
        cpasync16(dst + 4,  src + 4);
        cpasync16(dst + 8,  src + 8);
        cpasync16(dst + 12, src + 12);
    }
    {
        int krow = tid >> 3, c = (tid & 7)*16;
        const float* src = Bm + (size_t)(k0 + krow)*ldb + n0 + c;
        float* dst = bufB + krow*SB_ST + c;
        cpasync16(dst,      src);
        cpasync16(dst + 4,  src + 4);
        cpasync16(dst + 8,  src + 8);
        cpasync16(dst + 12, src + 12);
    }
    asm volatile("cp.async.commit_group;");
}

__global__ void __launch_bounds__(256, 2) mma_gemm(
    const float* __restrict__ A, const float* __restrict__ Bm, float* __restrict__ C,
    int K, int lda, int ldb, int ldc,
    const float* __restrict__ bias, const float* __restrict__ resid, int ldr, int relu,
    size_t batchA, size_t batchB, size_t batchC, float* stats)
{
    extern __shared__ float smem[];
    int z = blockIdx.z;
    A  += (size_t)z*batchA;
    Bm += (size_t)z*batchB;
    C  += (size_t)z*batchC;
    int tid = threadIdx.x, lane = tid & 31, warp = tid >> 5;
    int wm = warp & 1, wn = warp >> 1;       // warp tile: 64 (M) x 32 (N)
    int m0 = blockIdx.y*128, n0 = blockIdx.x*128;
    float acc[4][4][4];
#pragma unroll
    for (int a2 = 0; a2 < 4; a2++)
#pragma unroll
        for (int b2 = 0; b2 < 4; b2++)
#pragma unroll
            for (int c2 = 0; c2 < 4; c2++) acc[a2][b2][c2] = 0.0f;

    int nk = K >> 5;
    load_tile(smem, smem + TILE_A_W, A, Bm, lda, ldb, m0, n0, 0, tid);

    for (int it = 0; it < nk; it++) {
        asm volatile("cp.async.wait_group 0;");
        __syncthreads();   // also orders compute(it-1) before prefetch(it+1) overwrite
        int cur = it & 1;
        if (it + 1 < nk)
            load_tile(smem + (cur^1)*BUF_W, smem + (cur^1)*BUF_W + TILE_A_W,
                      A, Bm, lda, ldb, m0, n0, (it+1)*32, tid);
        const float* sA = smem + cur*BUF_W;
        const float* sB = sA + TILE_A_W;
#pragma unroll
        for (int kk = 0; kk < 4; kk++) {
            int kb = kk*8;
            unsigned af[4][4], bf[4][2];
#pragma unroll
            for (int mt = 0; mt < 4; mt++) {
                int r = wm*64 + mt*16 + (lane >> 2);
                int kc = kb + (lane & 3);
                af[mt][0] = f2tf(sA[r*SA_ST + kc]);
                af[mt][1] = f2tf(sA[(r+8)*SA_ST + kc]);
                af[mt][2] = f2tf(sA[r*SA_ST + kc + 4]);
                af[mt][3] = f2tf(sA[(r+8)*SA_ST + kc + 4]);
            }
#pragma unroll
            for (int nt = 0; nt < 4; nt++) {
                int c = wn*32 + nt*8 + (lane >> 2);
                int kr = kb + (lane & 3);
                bf[nt][0] = __float_as_uint(sB[kr*SB_ST + c]);       // B pre-rounded
                bf[nt][1] = __float_as_uint(sB[(kr+4)*SB_ST + c]);
            }
#pragma unroll
            for (int mt = 0; mt < 4; mt++)
#pragma unroll
                for (int nt = 0; nt < 4; nt++)
                    asm volatile(
                        "mma.sync.aligned.m16n8k8.row.col.f32.tf32.tf32.f32 "
                        "{%0,%1,%2,%3}, {%4,%5,%6,%7}, {%8,%9}, {%0,%1,%2,%3};"
                        : "+f"(acc[mt][nt][0]), "+f"(acc[mt][nt][1]),
                          "+f"(acc[mt][nt][2]), "+f"(acc[mt][nt][3])
                        : "r"(af[mt][0]), "r"(af[mt][1]), "r"(af[mt][2]), "r"(af[mt][3]),
                          "r"(bf[nt][0]), "r"(bf[nt][1]));
        }
    }
    // epilogue (+ optional per-column sum/sumsq for BN stats)
    float cs[4][2] = {}, cs2[4][2] = {};
#pragma unroll
    for (int mt = 0; mt < 4; mt++) {
#pragma unroll
        for (int nt = 0; nt < 4; nt++) {
            int r = m0 + wm*64 + mt*16 + (lane >> 2);
            int c = n0 + wn*32 + nt*8 + (lane & 3)*2;
#pragma unroll
            for (int half = 0; half < 2; half++) {
                int rr = r + half*8;
                float v0 = acc[mt][nt][half*2+0];
                float v1 = acc[mt][nt][half*2+1];
                if (bias)  { v0 += bias[c];  v1 += bias[c+1]; }
                if (relu)  { v0 = fmaxf(v0, 0.0f); v1 = fmaxf(v1, 0.0f); }
                if (resid) {
                    float2 rv = *(const float2*)&resid[(size_t)rr*ldr + c];
                    v0 += rv.x; v1 += rv.y;
                }
                *(float2*)&C[(size_t)rr*ldc + c] = make_float2(v0, v1);
                if (stats) {
                    cs[nt][0]  += v0;    cs[nt][1]  += v1;
                    cs2[nt][0] += v0*v0; cs2[nt][1] += v1*v1;
                }
            }
        }
    }
    if (stats) {
        float* red = smem;              // reuse stage memory
        __syncthreads();                // all warps done reading smem tiles
        if (tid < 256) { red[tid] = 0.0f; }
        __syncthreads();
#pragma unroll
        for (int nt = 0; nt < 4; nt++) {
#pragma unroll
            for (int j = 0; j < 2; j++) {
                float s = cs[nt][j], s2 = cs2[nt][j];
#pragma unroll
                for (int o = 16; o >= 4; o >>= 1) {
                    s  += __shfl_xor_sync(0xffffffffu, s,  o);
                    s2 += __shfl_xor_sync(0xffffffffu, s2, o);
                }
                if ((lane >> 2) == 0) {
                    int cc = wn*32 + nt*8 + (lane & 3)*2 + j;
                    atomicAdd(&red[cc], s);
                    atomicAdd(&red[128 + cc], s2);
                }
            }
        }
        __syncthreads();
        if (tid < 128) {
            atomicAdd(&stats[n0 + tid],      red[tid]);
            atomicAdd(&stats[EE + n0 + tid], red[128 + tid]);
        }
    }
}

// ---------------- adjacency predicate ----------------
__device__ __forceinline__ bool adj_fn(int g, int q, int k, int len, const int* fl) {
    if (q == k) return q < len;
    if (g == 0) {
        if (k == q+1) return fl[q] == 100 && q < len-1;
        if (q == k+1) return fl[k] == 100 && k < len-1;
        return false;
    } else if (g == 1) {
        if (k == q+1) return fl[q] == 100 && q < len-1;
        if (q == k+1) return fl[k] == 100 && k < len-1;
        if (k == q+2) return fl[q] == 100 && fl[q+1] == 100 && q < len-2;
        if (q == k+2) return fl[k] == 100 && fl[k+1] == 100 && k < len-2;
        return false;
    } else {
        if (q == 0 && k == len-1 && len > 1) return true;
        if (k == 0 && q == len-1 && len > 1) return true;
        if (k == q+1) return fl[q] == 101 && q < len-1;
        if (q == k+1) return fl[k] == 101 && k < len-1;
        return false;
    }
}

// ---------------- sparse attention: <=7 candidate keys per valid query ----------
__global__ void __launch_bounds__(256) attn_kernel(
    const float* __restrict__ qkv, float* __restrict__ heads)
{
    __shared__ float sPart[8][32];
    __shared__ float sVmean[32];
    __shared__ int   sFlag[SS];
    __shared__ int   sLenS;
    int b = blockIdx.x, h = blockIdx.y, g = blockIdx.z;
    int tid = threadIdx.x;
    const float* basep = qkv + (size_t)b*SS*QKVW + g*768 + h*DKK;
    {
        int d = tid & 31, chunk = tid >> 5;
        float s = 0.0f;
        for (int r = chunk*32; r < chunk*32 + 32; r++)
            s += basep[(size_t)r*QKVW + 512 + d];
        sPart[chunk][d] = s;
    }
    sFlag[tid] = g_flag[b*SS + tid];
    if (tid == 0) sLenS = g_len[b];
    __syncthreads();
    if (tid < 32) {
        float s = 0.0f;
#pragma unroll
        for (int c2 = 0; c2 < 8; c2++) s += sPart[c2][tid];
        sVmean[tid] = s * (1.0f/256.0f);
    }
    __syncthreads();
    int qi = tid, len = sLenS;
    float* op = heads + ((size_t)g*TT + b*SS + qi)*EE + h*DKK;
    if (qi >= len) {
#pragma unroll
        for (int j = 0; j < 8; j++)
            *(float4*)(op + j*4) = *(float4*)(&sVmean[j*4]);
        return;
    }
    float qr[32];
    const float* qp = basep + (size_t)qi*QKVW;
#pragma unroll
    for (int j = 0; j < 8; j++) {
        float4 t4 = *(const float4*)(qp + j*4);
        qr[j*4+0] = t4.x; qr[j*4+1] = t4.y; qr[j*4+2] = t4.z; qr[j*4+3] = t4.w;
    }
    int cand[8]; int nc = 0;
    int pot[7];  int np = 0;
    if (g == 2) pot[np++] = 0;
    pot[np++] = qi-2; pot[np++] = qi-1; pot[np++] = qi; pot[np++] = qi+1; pot[np++] = qi+2;
    if (g == 2) pot[np++] = len-1;
    for (int i = 0; i < np; i++) {
        int kk = pot[i];
        if (kk < 0 || kk >= SS) continue;
        if (!adj_fn(g, qi, kk, len, sFlag)) continue;
        bool dup = false;
        for (int u = 0; u < nc; u++) if (cand[u] == kk) dup = true;
        if (!dup) cand[nc++] = kk;
    }
    const float scale = 0.17677669529663687f;
    float lg[8];
    float m = -1e30f;
    for (int i = 0; i < nc; i++) {
        const float* kp = basep + (size_t)cand[i]*QKVW + 256;
        float dot = 0.0f;
#pragma unroll
        for (int j = 0; j < 8; j++) {
            float4 k4 = *(const float4*)(kp + j*4);
            dot += qr[j*4+0]*k4.x + qr[j*4+1]*k4.y + qr[j*4+2]*k4.z + qr[j*4+3]*k4.w;
        }
        lg[i] = dot * scale;
        m = fmaxf(m, lg[i]);
    }
    float ssum = 0.0f;
    float o[32];
#pragma unroll
    for (int d = 0; d < 32; d++) o[d] = 0.0f;
    for (int i = 0; i < nc; i++) {
        float p = expf(lg[i] - m);
        ssum += p;
        const float* vp = basep + (size_t)cand[i]*QKVW + 512;
#pragma unroll
        for (int j = 0; j < 8; j++) {
            float4 v4 = *(const float4*)(vp + j*4);
            o[j*4+0] += p*v4.x; o[j*4+1] += p*v4.y; o[j*4+2] += p*v4.z; o[j*4+3] += p*v4.w;
        }
    }
    float inv = 1.0f / ssum;
#pragma unroll
    for (int j = 0; j < 8; j++) {
        float4 w4 = make_float4(o[j*4+0]*inv, o[j*4+1]*inv, o[j*4+2]*inv, o[j*4+3]*inv);
        *(float4*)(op + j*4) = w4;
    }
}

// ---------------- BN stats from accumulated sums ----------------
__global__ void bn_stats_kernel(const float* __restrict__ sums) {
    int f = threadIdx.x;
    float mean = sums[f] * (1.0f/(float)TT);
    float var  = sums[EE + f] * (1.0f/(float)TT) - mean*mean;
    g_mean[f] = mean;
    g_rstd[f] = rsqrtf(var + 1e-5f);
}

__global__ void bn_norm_kernel(const float* __restrict__ in, float* __restrict__ outp,
                               const float* __restrict__ gamma, const float* __restrict__ beta) {
    int t = blockIdx.x, f = threadIdx.x;
    outp[(size_t)t*EE + f] = gamma[f]*(in[(size_t)t*EE + f] - g_mean[f])*g_rstd[f] + beta[f];
}

// ---------------- masked mean over S ----------------
__global__ void final_kernel(const float* __restrict__ mask, float* __restrict__ outp) {
    __shared__ float sM[SS];
    int b = blockIdx.x, e = threadIdx.x;
    sM[e] = mask[b*SS + e];
    __syncthreads();
    float acc = 0.0f;
    for (int s = 0; s < SS; s++) acc += g_x[(size_t)(b*SS + s)*EE + e]*sM[s];
    float denom = fmaxf((float)g_len[b], 1.0f);
    outp[b*EE + e] = acc/denom;
}

// ---------------- host orchestration (graph-capturable) ----------------
extern "C" void kernel_launch(void* const* d_in, const int* in_sizes, int n_in,
                              void* d_out, int out_size) {
    (void)in_sizes; (void)n_in; (void)out_size;
    const float* data = (const float*)d_in[0];
    const float* mask = (const float*)d_in[1];
    const float* Wc   = (const float*)d_in[2];
    const float* bc   = (const float*)d_in[3];
    const float* ftab = (const float*)d_in[4];
    const float* ptab = (const float*)d_in[5];
    const float* Wq   = (const float*)d_in[6];
    const float* Wk   = (const float*)d_in[7];
    const float* Wv   = (const float*)d_in[8];
    const float* Wo   = (const float*)d_in[9];
    const float* Wf   = (const float*)d_in[10];
    const float* bf   = (const float*)d_in[11];
    const float* g1   = (const float*)d_in[12];
    const float* b1   = (const float*)d_in[13];
    const float* Wff  = (const float*)d_in[14];
    const float* bff  = (const float*)d_in[15];
    const float* g2   = (const float*)d_in[16];
    const float* b2   = (const float*)d_in[17];
    float* outp = (float*)d_out;

    float *x, *qkv, *heads, *hcat, *h, *h2, *wqkv, *wo, *wf, *wff, *sums;
    cudaGetSymbolAddress((void**)&x,     g_x);
    cudaGetSymbolAddress((void**)&qkv,   g_qkv);
    cudaGetSymbolAddress((void**)&heads, g_heads);
    cudaGetSymbolAddress((void**)&hcat,  g_hcat);
    cudaGetSymbolAddress((void**)&h,     g_h);
    cudaGetSymbolAddress((void**)&h2,    g_h2);
    cudaGetSymbolAddress((void**)&wqkv,  g_wqkv);
    cudaGetSymbolAddress((void**)&wo,    g_wo);
    cudaGetSymbolAddress((void**)&wf,    g_wf);
    cudaGetSymbolAddress((void**)&wff,   g_wff);
    cudaGetSymbolAddress((void**)&sums,  g_sums);

    cudaFuncSetAttribute(mma_gemm, cudaFuncAttributeMaxDynamicSharedMemorySize, GEMM_SMEM);

    pack_w<<<(12*HH*EE*DKK)/256, 256>>>(Wq, Wk, Wv);
    round_copy<<<(12*EE*EE)/256, 256>>>(Wo,  wo,  12*EE*EE);
    round_copy<<<(LL*E3*EE)/256, 256>>>(Wf,  wf,  LL*E3*EE);
    round_copy<<<(LL*EE*EE)/256, 256>>>(Wff, wff, LL*EE*EE);
    flags_kernel<<<BB, SS>>>(data, mask);
    embed_kernel<<<TT, EE>>>(data, Wc, bc, ftab, ptab);

    for (int l = 0; l < LL; l++) {
        // qkv (all 3 groups): (TT,256) @ (256,2304)
        mma_gemm<<<dim3(QKVW/128, TT/128, 1), 256, GEMM_SMEM>>>(
            x, wqkv + (size_t)l*EE*QKVW, qkv,
            EE, EE, QKVW, QKVW, nullptr, nullptr, 0, 0, 0, 0, 0, nullptr);
        attn_kernel<<<dim3(BB, HH, 3), 256>>>(qkv, heads);
        // hcat[:, g*E:(g+1)*E] = x + heads_g @ Wo[l,g]   (z-batched over g)
        mma_gemm<<<dim3(EE/128, TT/128, 3), 256, GEMM_SMEM>>>(
            heads, wo + (size_t)l*3*EE*EE, hcat,
            EE, EE, EE, E3, nullptr, x, EE, 0,
            (size_t)TT*EE, (size_t)EE*EE, (size_t)EE, nullptr);
        // h = hcat @ Wf[l] + bf[l]   (+ BN stats in epilogue)
        cudaMemsetAsync(sums, 0, 2*EE*sizeof(float), 0);
        mma_gemm<<<dim3(EE/128, TT/128, 1), 256, GEMM_SMEM>>>(
            hcat, wf + (size_t)l*E3*EE, h,
            E3, E3, EE, EE, bf + l*EE, nullptr, 0, 0, 0, 0, 0, sums);
        bn_stats_kernel<<<1, EE>>>(sums);
        bn_norm_kernel<<<TT, EE>>>(h, h, g1 + l*EE, b1 + l*EE);
        // h2 = h + relu(h @ Wff[l] + bff[l])   (+ BN stats in epilogue)
        cudaMemsetAsync(sums, 0, 2*EE*sizeof(float), 0);
        mma_gemm<<<dim3(EE/128, TT/128, 1), 256, GEMM_SMEM>>>(
            h, wff + (size_t)l*EE*EE, h2,
            EE, EE, EE, EE, bff + l*EE, h, EE, 1, 0, 0, 0, sums);
        bn_stats_kernel<<<1, EE>>>(sums);
        bn_norm_kernel<<<TT, EE>>>(h2, x, g2 + l*EE, b2 + l*EE);
    }
    final_kernel<<<BB, EE>>>(mask, outp);
}

// round 9
// speedup vs baseline: 5.1947x; 1.1485x over previous
#include <cuda_runtime.h>

#define BB 32
#define SS 256
#define EE 256
#define HH 8
#define DKK 32
#define LL 4
#define TT (BB*SS)
#define E3 (3*EE)
#define QKVW 2304   // 3 groups * (q|k|v) * 256
#define XHW 1024    // x (256) | heads g0 g1 g2 (768)

// ---------------- scratch (static device arrays; no allocation) ----------------
__device__ float g_xh[TT*XHW];          // cols [0,256)=x, [256,1024)=heads
__device__ float g_qkv[TT*QKVW];
__device__ float g_h[TT*EE];
__device__ float g_h2[TT*EE];
__device__ float g_wqkv[LL*EE*QKVW];    // pre-rounded tf32
__device__ float g_wf[LL*E3*EE];        // pre-rounded tf32
__device__ float g_wff[LL*EE*EE];       // pre-rounded tf32
__device__ float g_wcomb[12*EE*EE];     // Wo_g @ Wf_g  (fp32)
__device__ float g_wbig[LL*XHW*EE];     // [SumWf ; Wcomb stacked], pre-rounded tf32
__device__ int   g_flag[TT];
__device__ int   g_len[BB];
__device__ float g_sums[2*EE];

__device__ __forceinline__ unsigned f2tf(float x) {
    unsigned r; asm("cvt.rna.tf32.f32 %0, %1;" : "=r"(r) : "f"(x)); return r;
}

// ---------------- weight packing: (l,g,H,E,DK) -> (l, E, g*768 + {q,k,v}*256 + h*32 + d)
__global__ void pack_w(const float* __restrict__ Wq, const float* __restrict__ Wk,
                       const float* __restrict__ Wv) {
    int id = blockIdx.x*blockDim.x + threadIdx.x;
    int d  = id % DKK;
    int e  = (id / DKK) % EE;
    int h  = (id / (DKK*EE)) % HH;
    int lg = id / (DKK*EE*HH);
    int l = lg / 3, g = lg % 3;
    size_t dst = ((size_t)l*EE + e)*QKVW + g*768 + h*DKK + d;
    g_wqkv[dst +   0] = __uint_as_float(f2tf(Wq[id]));
    g_wqkv[dst + 256] = __uint_as_float(f2tf(Wk[id]));
    g_wqkv[dst + 512] = __uint_as_float(f2tf(Wv[id]));
}

__global__ void round_copy(const float* __restrict__ src, float* __restrict__ dst, int n) {
    int i = blockIdx.x*blockDim.x + threadIdx.x;
    if (i < n) dst[i] = __uint_as_float(f2tf(src[i]));
}

// wbig[l]: row e<256 -> f2tf(sum_g Wf[l][g*256+e][n]); row 256+g*256+j -> f2tf(wcomb[(3l+g)][j][n])
__global__ void assemble_wbig(const float* __restrict__ Wf) {
    int id = blockIdx.x*blockDim.x + threadIdx.x;   // 0 .. LL*XHW*EE-1
    int n = id % EE;
    int row = (id / EE) % XHW;
    int l = id / (EE*XHW);
    float v;
    if (row < 256) {
        const float* wf = Wf + (size_t)l*E3*EE;
        v = Wf ? (wf[(size_t)row*EE + n] + wf[(size_t)(256+row)*EE + n] + wf[(size_t)(512+row)*EE + n]) : 0.0f;
    } else {
        int g = (row - 256) >> 8, j = (row - 256) & 255;
        v = g_wcomb[(size_t)(l*3 + g)*EE*EE + (size_t)j*EE + n];
    }
    g_wbig[id] = __uint_as_float(f2tf(v));
}

// ---------------- flags + lengths ----------------
__global__ void flags_kernel(const float* __restrict__ data, const float* __restrict__ mask) {
    int b = blockIdx.x, s = threadIdx.x;
    int idx = b*SS + s;
    float mk = mask[idx];
    float p1 = data[idx*5+2], p2 = data[idx*5+3], p3 = data[idx*5+4];
    int f = 0;
    if (p1 == 1.0f) f = 100;
    if (p2 == 1.0f || p3 == 1.0f) f = 101;
    if (mk == 0.0f) f = 102;
    g_flag[idx] = f;
    __shared__ float red[SS];
    red[s] = mk;
    __syncthreads();
    for (int st = 128; st > 0; st >>= 1) {
        if (s < st) red[s] += red[s+st];
        __syncthreads();
    }
    if (s == 0) g_len[b] = (int)(red[0] + 0.5f);
}

// ---------------- input embedding (into xh cols [0,256)) ----------------
__global__ void embed_kernel(const float* __restrict__ data, const float* __restrict__ Wc,
                             const float* __restrict__ bc, const float* __restrict__ ftab,
                             const float* __restrict__ ptab) {
    int t = blockIdx.x;
    int e = threadIdx.x;
    float c0 = data[t*5+0], c1 = data[t*5+1];
    int fl = g_flag[t];
    int s = t & (SS-1);
    g_xh[(size_t)t*XHW + e] = c0*Wc[e] + c1*Wc[EE+e] + bc[e] + ftab[fl*EE+e] + ptab[s*EE+e];
}

// ---------------- tf32 tensor-core GEMM with cp.async double buffering --------
__device__ __forceinline__ void cpasync16(float* dst, const float* src) {
    unsigned s = (unsigned)__cvta_generic_to_shared(dst);
    asm volatile("cp.async.cg.shared.global [%0], [%1], 16;" :: "r"(s), "l"(src));
}

#define SA_ST 36
#define SB_ST 136
#define TILE_A_W (128*SA_ST)
#define TILE_B_W (32*SB_ST)
#define BUF_W (TILE_A_W + TILE_B_W)
#define GEMM_SMEM (2*BUF_W*4)       // 71680 bytes

__device__ __forceinline__ void load_tile(float* bufA, float* bufB,
        const float* A, const float* Bm, int lda, int ldb,
        int m0, int n0, int k0, int tid)
{
    {
        int row = tid >> 1, c = (tid & 1)*16;
        const float* src = A + (size_t)(m0 + row)*lda + k0 + c;
        float* dst = bufA + row*SA_ST + c;
        cpasync16(dst,      src);
        cpasync16(dst + 4,  src + 4);
        cpasync16(dst + 8,  src + 8);
        cpasync16(dst + 12, src + 12);
    }
    {
        int krow = tid >> 3, c = (tid & 7)*16;
        const float* src = Bm + (size_t)(k0 + krow)*ldb + n0 + c;
        float* dst = bufB + krow*SB_ST + c;
        cpasync16(dst,      src);
        cpasync16(dst + 4,  src + 4);
        cpasync16(dst + 8,  src + 8);
        cpasync16(dst + 12, src + 12);
    }
    asm volatile("cp.async.commit_group;");
}

__global__ void __launch_bounds__(256, 2) mma_gemm(
    const float* __restrict__ A, const float* __restrict__ Bm, float* __restrict__ C,
    int K, int lda, int ldb, int ldc,
    const float* __restrict__ bias, const float* __restrict__ resid, int ldr, int relu,
    size_t batchA, size_t batchB, size_t batchC, float* stats)
{
    extern __shared__ float smem[];
    int z = blockIdx.z;
    A  += (size_t)z*batchA;
    Bm += (size_t)z*batchB;
    C  += (size_t)z*batchC;
    int tid = threadIdx.x, lane = tid & 31, warp = tid >> 5;
    int wm = warp & 1, wn = warp >> 1;       // warp tile: 64 (M) x 32 (N)
    int m0 = blockIdx.y*128, n0 = blockIdx.x*128;
    float acc[4][4][4];
#pragma unroll
    for (int a2 = 0; a2 < 4; a2++)
#pragma unroll
        for (int b2 = 0; b2 < 4; b2++)
#pragma unroll
            for (int c2 = 0; c2 < 4; c2++) acc[a2][b2][c2] = 0.0f;

    int nk = K >> 5;
    load_tile(smem, smem + TILE_A_W, A, Bm, lda, ldb, m0, n0, 0, tid);

    for (int it = 0; it < nk; it++) {
        asm volatile("cp.async.wait_group 0;");
        __syncthreads();   // orders compute(it-1) before prefetch(it+1) overwrite
        int cur = it & 1;
        if (it + 1 < nk)
            load_tile(smem + (cur^1)*BUF_W, smem + (cur^1)*BUF_W + TILE_A_W,
                      A, Bm, lda, ldb, m0, n0, (it+1)*32, tid);
        const float* sA = smem + cur*BUF_W;
        const float* sB = sA + TILE_A_W;
#pragma unroll
        for (int kk = 0; kk < 4; kk++) {
            int kb = kk*8;
            unsigned af[4][4], bf[4][2];
#pragma unroll
            for (int mt = 0; mt < 4; mt++) {
                int r = wm*64 + mt*16 + (lane >> 2);
                int kc = kb + (lane & 3);
                af[mt][0] = f2tf(sA[r*SA_ST + kc]);
                af[mt][1] = f2tf(sA[(r+8)*SA_ST + kc]);
                af[mt][2] = f2tf(sA[r*SA_ST + kc + 4]);
                af[mt][3] = f2tf(sA[(r+8)*SA_ST + kc + 4]);
            }
#pragma unroll
            for (int nt = 0; nt < 4; nt++) {
                int c = wn*32 + nt*8 + (lane >> 2);
                int kr = kb + (lane & 3);
                bf[nt][0] = __float_as_uint(sB[kr*SB_ST + c]);       // B pre-rounded
                bf[nt][1] = __float_as_uint(sB[(kr+4)*SB_ST + c]);
            }
#pragma unroll
            for (int mt = 0; mt < 4; mt++)
#pragma unroll
                for (int nt = 0; nt < 4; nt++)
                    asm volatile(
                        "mma.sync.aligned.m16n8k8.row.col.f32.tf32.tf32.f32 "
                        "{%0,%1,%2,%3}, {%4,%5,%6,%7}, {%8,%9}, {%0,%1,%2,%3};"
                        : "+f"(acc[mt][nt][0]), "+f"(acc[mt][nt][1]),
                          "+f"(acc[mt][nt][2]), "+f"(acc[mt][nt][3])
                        : "r"(af[mt][0]), "r"(af[mt][1]), "r"(af[mt][2]), "r"(af[mt][3]),
                          "r"(bf[nt][0]), "r"(bf[nt][1]));
        }
    }
    // epilogue (+ optional per-column sum/sumsq for BN stats)
    float cs[4][2] = {}, cs2[4][2] = {};
#pragma unroll
    for (int mt = 0; mt < 4; mt++) {
#pragma unroll
        for (int nt = 0; nt < 4; nt++) {
            int r = m0 + wm*64 + mt*16 + (lane >> 2);
            int c = n0 + wn*32 + nt*8 + (lane & 3)*2;
#pragma unroll
            for (int half = 0; half < 2; half++) {
                int rr = r + half*8;
                float v0 = acc[mt][nt][half*2+0];
                float v1 = acc[mt][nt][half*2+1];
                if (bias)  { v0 += bias[c];  v1 += bias[c+1]; }
                if (relu)  { v0 = fmaxf(v0, 0.0f); v1 = fmaxf(v1, 0.0f); }
                if (resid) {
                    float2 rv = *(const float2*)&resid[(size_t)rr*ldr + c];
                    v0 += rv.x; v1 += rv.y;
                }
                *(float2*)&C[(size_t)rr*ldc + c] = make_float2(v0, v1);
                if (stats) {
                    cs[nt][0]  += v0;    cs[nt][1]  += v1;
                    cs2[nt][0] += v0*v0; cs2[nt][1] += v1*v1;
                }
            }
        }
    }
    if (stats) {
        float* red = smem;
        __syncthreads();
        if (tid < 256) { red[tid] = 0.0f; }
        __syncthreads();
#pragma unroll
        for (int nt = 0; nt < 4; nt++) {
#pragma unroll
            for (int j = 0; j < 2; j++) {
                float s = cs[nt][j], s2 = cs2[nt][j];
#pragma unroll
                for (int o = 16; o >= 4; o >>= 1) {
                    s  += __shfl_xor_sync(0xffffffffu, s,  o);
                    s2 += __shfl_xor_sync(0xffffffffu, s2, o);
                }
                if ((lane >> 2) == 0) {
                    int cc = wn*32 + nt*8 + (lane & 3)*2 + j;
                    atomicAdd(&red[cc], s);
                    atomicAdd(&red[128 + cc], s2);
                }
            }
        }
        __syncthreads();
        if (tid < 128) {
            atomicAdd(&stats[n0 + tid],      red[tid]);
            atomicAdd(&stats[EE + n0 + tid], red[128 + tid]);
        }
    }
}

// ---------------- adjacency predicate ----------------
__device__ __forceinline__ bool adj_fn(int g, int q, int k, int len, const int* fl) {
    if (q == k) return q < len;
    if (g == 0) {
        if (k == q+1) return fl[q] == 100 && q < len-1;
        if (q == k+1) return fl[k] == 100 && k < len-1;
        return false;
    } else if (g == 1) {
        if (k == q+1) return fl[q] == 100 && q < len-1;
        if (q == k+1) return fl[k] == 100 && k < len-1;
        if (k == q+2) return fl[q] == 100 && fl[q+1] == 100 && q < len-2;
        if (q == k+2) return fl[k] == 100 && fl[k+1] == 100 && k < len-2;
        return false;
    } else {
        if (q == 0 && k == len-1 && len > 1) return true;
        if (k == 0 && q == len-1 && len > 1) return true;
        if (k == q+1) return fl[q] == 101 && q < len-1;
        if (q == k+1) return fl[k] == 101 && k < len-1;
        return false;
    }
}

// ---------------- sparse attention: writes into xh cols [256+g*256, ...) -------
__global__ void __launch_bounds__(256) attn_kernel(
    const float* __restrict__ qkv, float* __restrict__ xh)
{
    __shared__ float sPart[8][32];
    __shared__ float sVmean[32];
    __shared__ int   sFlag[SS];
    __shared__ int   sLenS;
    int b = blockIdx.x, h = blockIdx.y, g = blockIdx.z;
    int tid = threadIdx.x;
    const float* basep = qkv + (size_t)b*SS*QKVW + g*768 + h*DKK;
    {
        int d = tid & 31, chunk = tid >> 5;
        float s = 0.0f;
        for (int r = chunk*32; r < chunk*32 + 32; r++)
            s += basep[(size_t)r*QKVW + 512 + d];
        sPart[chunk][d] = s;
    }
    sFlag[tid] = g_flag[b*SS + tid];
    if (tid == 0) sLenS = g_len[b];
    __syncthreads();
    if (tid < 32) {
        float s = 0.0f;
#pragma unroll
        for (int c2 = 0; c2 < 8; c2++) s += sPart[c2][tid];
        sVmean[tid] = s * (1.0f/256.0f);
    }
    __syncthreads();
    int qi = tid, len = sLenS;
    float* op = xh + (size_t)(b*SS + qi)*XHW + 256 + g*256 + h*DKK;
    if (qi >= len) {
#pragma unroll
        for (int j = 0; j < 8; j++)
            *(float4*)(op + j*4) = *(float4*)(&sVmean[j*4]);
        return;
    }
    float qr[32];
    const float* qp = basep + (size_t)qi*QKVW;
#pragma unroll
    for (int j = 0; j < 8; j++) {
        float4 t4 = *(const float4*)(qp + j*4);
        qr[j*4+0] = t4.x; qr[j*4+1] = t4.y; qr[j*4+2] = t4.z; qr[j*4+3] = t4.w;
    }
    int cand[8]; int nc = 0;
    int pot[7];  int np = 0;
    if (g == 2) pot[np++] = 0;
    pot[np++] = qi-2; pot[np++] = qi-1; pot[np++] = qi; pot[np++] = qi+1; pot[np++] = qi+2;
    if (g == 2) pot[np++] = len-1;
    for (int i = 0; i < np; i++) {
        int kk = pot[i];
        if (kk < 0 || kk >= SS) continue;
        if (!adj_fn(g, qi, kk, len, sFlag)) continue;
        bool dup = false;
        for (int u = 0; u < nc; u++) if (cand[u] == kk) dup = true;
        if (!dup) cand[nc++] = kk;
    }
    const float scale = 0.17677669529663687f;
    float lg[8];
    float m = -1e30f;
    for (int i = 0; i < nc; i++) {
        const float* kp = basep + (size_t)cand[i]*QKVW + 256;
        float dot = 0.0f;
#pragma unroll
        for (int j = 0; j < 8; j++) {
            float4 k4 = *(const float4*)(kp + j*4);
            dot += qr[j*4+0]*k4.x + qr[j*4+1]*k4.y + qr[j*4+2]*k4.z + qr[j*4+3]*k4.w;
        }
        lg[i] = dot * scale;
        m = fmaxf(m, lg[i]);
    }
    float ssum = 0.0f;
    float o[32];
#pragma unroll
    for (int d = 0; d < 32; d++) o[d] = 0.0f;
    for (int i = 0; i < nc; i++) {
        float p = expf(lg[i] - m);
        ssum += p;
        const float* vp = basep + (size_t)cand[i]*QKVW + 512;
#pragma unroll
        for (int j = 0; j < 8; j++) {
            float4 v4 = *(const float4*)(vp + j*4);
            o[j*4+0] += p*v4.x; o[j*4+1] += p*v4.y; o[j*4+2] += p*v4.z; o[j*4+3] += p*v4.w;
        }
    }
    float inv = 1.0f / ssum;
#pragma unroll
    for (int j = 0; j < 8; j++) {
        float4 w4 = make_float4(o[j*4+0]*inv, o[j*4+1]*inv, o[j*4+2]*inv, o[j*4+3]*inv);
        *(float4*)(op + j*4) = w4;
    }
}

// ---------------- BN normalize (stats computed inline from sums) --------------
__global__ void __launch_bounds__(256) bn_norm_kernel(
    const float* __restrict__ in, float* __restrict__ outp,
    const float* __restrict__ gamma, const float* __restrict__ beta,
    const float* __restrict__ sums, int out_ld)
{
    int tid = threadIdx.x;
    int f = (tid & 63)*4;
    int t = blockIdx.x*4 + (tid >> 6);
    float4 s  = *(const float4*)&sums[f];
    float4 s2 = *(const float4*)&sums[EE + f];
    const float invN = 1.0f/(float)TT;
    float m0 = s.x*invN, m1 = s.y*invN, m2 = s.z*invN, m3 = s.w*invN;
    float r0 = rsqrtf(s2.x*invN - m0*m0 + 1e-5f);
    float r1 = rsqrtf(s2.y*invN - m1*m1 + 1e-5f);
    float r2 = rsqrtf(s2.z*invN - m2*m2 + 1e-5f);
    float r3 = rsqrtf(s2.w*invN - m3*m3 + 1e-5f);
    float4 v  = *(const float4*)&in[(size_t)t*EE + f];
    float4 gm = *(const float4*)&gamma[f];
    float4 bt = *(const float4*)&beta[f];
    float4 o;
    o.x = gm.x*(v.x - m0)*r0 + bt.x;
    o.y = gm.y*(v.y - m1)*r1 + bt.y;
    o.z = gm.z*(v.z - m2)*r2 + bt.z;
    o.w = gm.w*(v.w - m3)*r3 + bt.w;
    *(float4*)&outp[(size_t)t*out_ld + f] = o;
}

// ---------------- masked mean over S ----------------
__global__ void final_kernel(const float* __restrict__ mask, float* __restrict__ outp) {
    __shared__ float sM[SS];
    int b = blockIdx.x, e = threadIdx.x;
    sM[e] = mask[b*SS + e];
    __syncthreads();
    float acc = 0.0f;
    for (int s = 0; s < SS; s++) acc += g_xh[(size_t)(b*SS + s)*XHW + e]*sM[s];
    float denom = fmaxf((float)g_len[b], 1.0f);
    outp[b*EE + e] = acc/denom;
}

// ---------------- host orchestration (graph-capturable) ----------------
extern "C" void kernel_launch(void* const* d_in, const int* in_sizes, int n_in,
                              void* d_out, int out_size) {
    (void)in_sizes; (void)n_in; (void)out_size;
    const float* data = (const float*)d_in[0];
    const float* mask = (const float*)d_in[1];
    const float* Wc   = (const float*)d_in[2];
    const float* bc   = (const float*)d_in[3];
    const float* ftab = (const float*)d_in[4];
    const float* ptab = (const float*)d_in[5];
    const float* Wq   = (const float*)d_in[6];
    const float* Wk   = (const float*)d_in[7];
    const float* Wv   = (const float*)d_in[8];
    const float* Wo   = (const float*)d_in[9];
    const float* Wf   = (const float*)d_in[10];
    const float* bf   = (const float*)d_in[11];
    const float* g1   = (const float*)d_in[12];
    const float* b1   = (const float*)d_in[13];
    const float* Wff  = (const float*)d_in[14];
    const float* bff  = (const float*)d_in[15];
    const float* g2   = (const float*)d_in[16];
    const float* b2   = (const float*)d_in[17];
    float* outp = (float*)d_out;

    float *xh, *qkv, *h, *h2, *wqkv, *wf, *wff, *wcomb, *wbig, *sums;
    cudaGetSymbolAddress((void**)&xh,    g_xh);
    cudaGetSymbolAddress((void**)&qkv,   g_qkv);
    cudaGetSymbolAddress((void**)&h,     g_h);
    cudaGetSymbolAddress((void**)&h2,    g_h2);
    cudaGetSymbolAddress((void**)&wqkv,  g_wqkv);
    cudaGetSymbolAddress((void**)&wf,    g_wf);
    cudaGetSymbolAddress((void**)&wff,   g_wff);
    cudaGetSymbolAddress((void**)&wcomb, g_wcomb);
    cudaGetSymbolAddress((void**)&wbig,  g_wbig);
    cudaGetSymbolAddress((void**)&sums,  g_sums);

    cudaFuncSetAttribute(mma_gemm, cudaFuncAttributeMaxDynamicSharedMemorySize, GEMM_SMEM);

    // -------- weight precompute --------
    pack_w<<<(12*HH*EE*DKK)/256, 256>>>(Wq, Wk, Wv);
    round_copy<<<(LL*E3*EE)/256, 256>>>(Wf,  wf,  LL*E3*EE);
    round_copy<<<(LL*EE*EE)/256, 256>>>(Wff, wff, LL*EE*EE);
    // wcomb[z] = Wo[z] (256x256) @ wf block z (256x256), z = l*3+g
    mma_gemm<<<dim3(2, 2, 12), 256, GEMM_SMEM>>>(
        Wo, wf, wcomb, EE, EE, EE, EE, nullptr, nullptr, 0, 0,
        (size_t)EE*EE, (size_t)EE*EE, (size_t)EE*EE, nullptr);
    assemble_wbig<<<(LL*XHW*EE)/256, 256>>>(Wf);

    // -------- activations --------
    flags_kernel<<<BB, SS>>>(data, mask);
    embed_kernel<<<TT, EE>>>(data, Wc, bc, ftab, ptab);

    for (int l = 0; l < LL; l++) {
        // qkv: xh[:, :256] @ wqkv[l]  -> (TT, 2304)
        mma_gemm<<<dim3(QKVW/128, TT/128, 1), 256, GEMM_SMEM>>>(
            xh, wqkv + (size_t)l*EE*QKVW, qkv,
            EE, XHW, QKVW, QKVW, nullptr, nullptr, 0, 0, 0, 0, 0, nullptr);
        attn_kernel<<<dim3(BB, HH, 3), 256>>>(qkv, xh);
        // h = [x | heads] @ wbig[l] + bf[l]  (K=1024, stats fused)
        cudaMemsetAsync(sums, 0, 2*EE*sizeof(float), 0);
        mma_gemm<<<dim3(EE/128, TT/128, 1), 256, GEMM_SMEM>>>(
            xh, wbig + (size_t)l*XHW*EE, h,
            XHW, XHW, EE, EE, bf + l*EE, nullptr, 0, 0, 0, 0, 0, sums);
        bn_norm_kernel<<<TT/4, 256>>>(h, h, g1 + l*EE, b1 + l*EE, sums, EE);
        // h2 = h + relu(h @ Wff[l] + bff[l])  (stats fused)
        cudaMemsetAsync(sums, 0, 2*EE*sizeof(float), 0);
        mma_gemm<<<dim3(EE/128, TT/128, 1), 256, GEMM_SMEM>>>(
            h, wff + (size_t)l*EE*EE, h2,
            EE, EE, EE, EE, bff + l*EE, h, EE, 1, 0, 0, 0, sums);
        bn_norm_kernel<<<TT/4, 256>>>(h2, xh, g2 + l*EE, b2 + l*EE, sums, XHW);
    }
    final_kernel<<<BB, EE>>>(mask, outp);
}

// round 10
// speedup vs baseline: 5.1959x; 1.0002x over previous
#include <cuda_runtime.h>

#define BB 32
#define SS 256
#define EE 256
#define HH 8
#define DKK 32
#define LL 4
#define TT (BB*SS)
#define E3 (3*EE)
#define QKVW 2304   // 3 groups * (q|k|v) * 256
#define XHW 1024    // x (256) | heads g0 g1 g2 (768)

// ---------------- scratch (static device arrays; no allocation) ----------------
__device__ float g_xh[TT*XHW];          // cols [0,256)=x, [256,1024)=heads
__device__ float g_qkv[TT*QKVW];
__device__ float g_h[TT*EE];
__device__ float g_h2[TT*EE];
__device__ float g_wqkv[LL*EE*QKVW];    // pre-rounded tf32
__device__ float g_wf[LL*E3*EE];        // pre-rounded tf32
__device__ float g_wff[LL*EE*EE];       // pre-rounded tf32
__device__ float g_wcomb[12*EE*EE];     // Wo_g @ Wf_g  (fp32)
__device__ float g_wbig[LL*XHW*EE];     // [SumWf ; Wcomb stacked], pre-rounded tf32
__device__ int   g_flag[TT];
__device__ int   g_len[BB];
__device__ float g_sums[2*EE];

__device__ __forceinline__ unsigned f2tf(float x) {
    unsigned r; asm("cvt.rna.tf32.f32 %0, %1;" : "=r"(r) : "f"(x)); return r;
}

// ---------------- weight packing: (l,g,H,E,DK) -> (l, E, g*768 + {q,k,v}*256 + h*32 + d)
__global__ void pack_w(const float* __restrict__ Wq, const float* __restrict__ Wk,
                       const float* __restrict__ Wv) {
    int id = blockIdx.x*blockDim.x + threadIdx.x;
    int d  = id % DKK;
    int e  = (id / DKK) % EE;
    int h  = (id / (DKK*EE)) % HH;
    int lg = id / (DKK*EE*HH);
    int l = lg / 3, g = lg % 3;
    size_t dst = ((size_t)l*EE + e)*QKVW + g*768 + h*DKK + d;
    g_wqkv[dst +   0] = __uint_as_float(f2tf(Wq[id]));
    g_wqkv[dst + 256] = __uint_as_float(f2tf(Wk[id]));
    g_wqkv[dst + 512] = __uint_as_float(f2tf(Wv[id]));
}

__global__ void round_copy(const float* __restrict__ src, float* __restrict__ dst, int n) {
    int i = blockIdx.x*blockDim.x + threadIdx.x;
    if (i < n) dst[i] = __uint_as_float(f2tf(src[i]));
}

// wbig[l]: row e<256 -> f2tf(sum_g Wf[l][g*256+e][n]); row 256+g*256+j -> f2tf(wcomb[(3l+g)][j][n])
__global__ void assemble_wbig(const float* __restrict__ Wf) {
    int id = blockIdx.x*blockDim.x + threadIdx.x;   // 0 .. LL*XHW*EE-1
    int n = id % EE;
    int row = (id / EE) % XHW;
    int l = id / (EE*XHW);
    float v;
    if (row < 256) {
        const float* wf = Wf + (size_t)l*E3*EE;
        v = Wf ? (wf[(size_t)row*EE + n] + wf[(size_t)(256+row)*EE + n] + wf[(size_t)(512+row)*EE + n]) : 0.0f;
    } else {
        int g = (row - 256) >> 8, j = (row - 256) & 255;
        v = g_wcomb[(size_t)(l*3 + g)*EE*EE + (size_t)j*EE + n];
    }
    g_wbig[id] = __uint_as_float(f2tf(v));
}

// ---------------- flags + lengths ----------------
__global__ void flags_kernel(const float* __restrict__ data, const float* __restrict__ mask) {
    int b = blockIdx.x, s = threadIdx.x;
    int idx = b*SS + s;
    float mk = mask[idx];
    float p1 = data[idx*5+2], p2 = data[idx*5+3], p3 = data[idx*5+4];
    int f = 0;
    if (p1 == 1.0f) f = 100;
    if (p2 == 1.0f || p3 == 1.0f) f = 101;
    if (mk == 0.0f) f = 102;
    g_flag[idx] = f;
    __shared__ float red[SS];
    red[s] = mk;
    __syncthreads();
    for (int st = 128; st > 0; st >>= 1) {
        if (s < st) red[s] += red[s+st];
        __syncthreads();
    }
    if (s == 0) g_len[b] = (int)(red[0] + 0.5f);
}

// ---------------- input embedding (into xh cols [0,256)) ----------------
__global__ void embed_kernel(const float* __restrict__ data, const float* __restrict__ Wc,
                             const float* __restrict__ bc, const float* __restrict__ ftab,
                             const float* __restrict__ ptab) {
    int t = blockIdx.x;
    int e = threadIdx.x;
    float c0 = data[t*5+0], c1 = data[t*5+1];
    int fl = g_flag[t];
    int s = t & (SS-1);
    g_xh[(size_t)t*XHW + e] = c0*Wc[e] + c1*Wc[EE+e] + bc[e] + ftab[fl*EE+e] + ptab[s*EE+e];
}

// ---------------- tf32 tensor-core GEMM with cp.async double buffering --------
__device__ __forceinline__ void cpasync16(float* dst, const float* src) {
    unsigned s = (unsigned)__cvta_generic_to_shared(dst);
    asm volatile("cp.async.cg.shared.global [%0], [%1], 16;" :: "r"(s), "l"(src));
}

#define SA_ST 36
#define SB_ST 136
#define TILE_A_W (128*SA_ST)
#define TILE_B_W (32*SB_ST)
#define BUF_W (TILE_A_W + TILE_B_W)
#define GEMM_SMEM (2*BUF_W*4)       // 71680 bytes

__device__ __forceinline__ void load_tile(float* bufA, float* bufB,
        const float* A, const float* Bm, int lda, int ldb,
        int m0, int n0, int k0, int tid)
{
    {
        int row = tid >> 1, c = (tid & 1)*16;
        const float* src = A + (size_t)(m0 + row)*lda + k0 + c;
        float* dst = bufA + row*SA_ST + c;
        cpasync16(dst,      src);
        cpasync16(dst + 4,  src + 4);
        cpasync16(dst + 8,  src + 8);
        cpasync16(dst + 12, src + 12);
    }
    {
        int krow = tid >> 3, c = (tid & 7)*16;
        const float* src = Bm + (size_t)(k0 + krow)*ldb + n0 + c;
        float* dst = bufB + krow*SB_ST + c;
        cpasync16(dst,      src);
        cpasync16(dst + 4,  src + 4);
        cpasync16(dst + 8,  src + 8);
        cpasync16(dst + 12, src + 12);
    }
    asm volatile("cp.async.commit_group;");
}

__global__ void __launch_bounds__(256, 2) mma_gemm(
    const float* __restrict__ A, const float* __restrict__ Bm, float* __restrict__ C,
    int K, int lda, int ldb, int ldc,
    const float* __restrict__ bias, const float* __restrict__ resid, int ldr, int relu,
    size_t batchA, size_t batchB, size_t batchC, float* stats)
{
    extern __shared__ float smem[];
    int z = blockIdx.z;
    A  += (size_t)z*batchA;
    Bm += (size_t)z*batchB;
    C  += (size_t)z*batchC;
    int tid = threadIdx.x, lane = tid & 31, warp = tid >> 5;
    int wm = warp & 1, wn = warp >> 1;       // warp tile: 64 (M) x 32 (N)
    int m0 = blockIdx.y*128, n0 = blockIdx.x*128;
    float acc[4][4][4];
#pragma unroll
    for (int a2 = 0; a2 < 4; a2++)
#pragma unroll
        for (int b2 = 0; b2 < 4; b2++)
#pragma unroll
            for (int c2 = 0; c2 < 4; c2++) acc[a2][b2][c2] = 0.0f;

    int nk = K >> 5;
    load_tile(smem, smem + TILE_A_W, A, Bm, lda, ldb, m0, n0, 0, tid);

    for (int it = 0; it < nk; it++) {
        asm volatile("cp.async.wait_group 0;");
        __syncthreads();   // orders compute(it-1) before prefetch(it+1) overwrite
        int cur = it & 1;
        if (it + 1 < nk)
            load_tile(smem + (cur^1)*BUF_W, smem + (cur^1)*BUF_W + TILE_A_W,
                      A, Bm, lda, ldb, m0, n0, (it+1)*32, tid);
        const float* sA = smem + cur*BUF_W;
        const float* sB = sA + TILE_A_W;
#pragma unroll
        for (int kk = 0; kk < 4; kk++) {
            int kb = kk*8;
            unsigned af[4][4], bf[4][2];
#pragma unroll
            for (int mt = 0; mt < 4; mt++) {
                int r = wm*64 + mt*16 + (lane >> 2);
                int kc = kb + (lane & 3);
                af[mt][0] = f2tf(sA[r*SA_ST + kc]);
                af[mt][1] = f2tf(sA[(r+8)*SA_ST + kc]);
                af[mt][2] = f2tf(sA[r*SA_ST + kc + 4]);
                af[mt][3] = f2tf(sA[(r+8)*SA_ST + kc + 4]);
            }
#pragma unroll
            for (int nt = 0; nt < 4; nt++) {
                int c = wn*32 + nt*8 + (lane >> 2);
                int kr = kb + (lane & 3);
                bf[nt][0] = __float_as_uint(sB[kr*SB_ST + c]);       // B pre-rounded
                bf[nt][1] = __float_as_uint(sB[(kr+4)*SB_ST + c]);
            }
#pragma unroll
            for (int mt = 0; mt < 4; mt++)
#pragma unroll
                for (int nt = 0; nt < 4; nt++)
                    asm volatile(
                        "mma.sync.aligned.m16n8k8.row.col.f32.tf32.tf32.f32 "
                        "{%0,%1,%2,%3}, {%4,%5,%6,%7}, {%8,%9}, {%0,%1,%2,%3};"
                        : "+f"(acc[mt][nt][0]), "+f"(acc[mt][nt][1]),
                          "+f"(acc[mt][nt][2]), "+f"(acc[mt][nt][3])
                        : "r"(af[mt][0]), "r"(af[mt][1]), "r"(af[mt][2]), "r"(af[mt][3]),
                          "r"(bf[nt][0]), "r"(bf[nt][1]));
        }
    }
    // epilogue (+ optional per-column sum/sumsq for BN stats)
    float cs[4][2] = {}, cs2[4][2] = {};
#pragma unroll
    for (int mt = 0; mt < 4; mt++) {
#pragma unroll
        for (int nt = 0; nt < 4; nt++) {
            int r = m0 + wm*64 + mt*16 + (lane >> 2);
            int c = n0 + wn*32 + nt*8 + (lane & 3)*2;
#pragma unroll
            for (int half = 0; half < 2; half++) {
                int rr = r + half*8;
                float v0 = acc[mt][nt][half*2+0];
                float v1 = acc[mt][nt][half*2+1];
                if (bias)  { v0 += bias[c];  v1 += bias[c+1]; }
                if (relu)  { v0 = fmaxf(v0, 0.0f); v1 = fmaxf(v1, 0.0f); }
                if (resid) {
                    float2 rv = *(const float2*)&resid[(size_t)rr*ldr + c];
                    v0 += rv.x; v1 += rv.y;
                }
                *(float2*)&C[(size_t)rr*ldc + c] = make_float2(v0, v1);
                if (stats) {
                    cs[nt][0]  += v0;    cs[nt][1]  += v1;
                    cs2[nt][0] += v0*v0; cs2[nt][1] += v1*v1;
                }
            }
        }
    }
    if (stats) {
        float* red = smem;
        __syncthreads();
        if (tid < 256) { red[tid] = 0.0f; }
        __syncthreads();
#pragma unroll
        for (int nt = 0; nt < 4; nt++) {
#pragma unroll
            for (int j = 0; j < 2; j++) {
                float s = cs[nt][j], s2 = cs2[nt][j];
#pragma unroll
                for (int o = 16; o >= 4; o >>= 1) {
                    s  += __shfl_xor_sync(0xffffffffu, s,  o);
                    s2 += __shfl_xor_sync(0xffffffffu, s2, o);
                }
                if ((lane >> 2) == 0) {
                    int cc = wn*32 + nt*8 + (lane & 3)*2 + j;
                    atomicAdd(&red[cc], s);
                    atomicAdd(&red[128 + cc], s2);
                }
            }
        }
        __syncthreads();
        if (tid < 128) {
            atomicAdd(&stats[n0 + tid],      red[tid]);
            atomicAdd(&stats[EE + n0 + tid], red[128 + tid]);
        }
    }
}

// ---------------- adjacency predicate ----------------
__device__ __forceinline__ bool adj_fn(int g, int q, int k, int len, const int* fl) {
    if (q == k) return q < len;
    if (g == 0) {
        if (k == q+1) return fl[q] == 100 && q < len-1;
        if (q == k+1) return fl[k] == 100 && k < len-1;
        return false;
    } else if (g == 1) {
        if (k == q+1) return fl[q] == 100 && q < len-1;
        if (q == k+1) return fl[k] == 100 && k < len-1;
        if (k == q+2) return fl[q] == 100 && fl[q+1] == 100 && q < len-2;
        if (q == k+2) return fl[k] == 100 && fl[k+1] == 100 && k < len-2;
        return false;
    } else {
        if (q == 0 && k == len-1 && len > 1) return true;
        if (k == 0 && q == len-1 && len > 1) return true;
        if (k == q+1) return fl[q] == 101 && q < len-1;
        if (q == k+1) return fl[k] == 101 && k < len-1;
        return false;
    }
}

// ---------------- sparse attention: writes into xh cols [256+g*256, ...) -------
__global__ void __launch_bounds__(256) attn_kernel(
    const float* __restrict__ qkv, float* __restrict__ xh)
{
    __shared__ float sPart[8][32];
    __shared__ float sVmean[32];
    __shared__ int   sFlag[SS];
    __shared__ int   sLenS;
    int b = blockIdx.x, h = blockIdx.y, g = blockIdx.z;
    int tid = threadIdx.x;
    const float* basep = qkv + (size_t)b*SS*QKVW + g*768 + h*DKK;
    {
        int d = tid & 31, chunk = tid >> 5;
        float s = 0.0f;
        for (int r = chunk*32; r < chunk*32 + 32; r++)
            s += basep[(size_t)r*QKVW + 512 + d];
        sPart[chunk][d] = s;
    }
    sFlag[tid] = g_flag[b*SS + tid];
    if (tid == 0) sLenS = g_len[b];
    __syncthreads();
    if (tid < 32) {
        float s = 0.0f;
#pragma unroll
        for (int c2 = 0; c2 < 8; c2++) s += sPart[c2][tid];
        sVmean[tid] = s * (1.0f/256.0f);
    }
    __syncthreads();
    int qi = tid, len = sLenS;
    float* op = xh + (size_t)(b*SS + qi)*XHW + 256 + g*256 + h*DKK;
    if (qi >= len) {
#pragma unroll
        for (int j = 0; j < 8; j++)
            *(float4*)(op + j*4) = *(float4*)(&sVmean[j*4]);
        return;
    }
    float qr[32];
    const float* qp = basep + (size_t)qi*QKVW;
#pragma unroll
    for (int j = 0; j < 8; j++) {
        float4 t4 = *(const float4*)(qp + j*4);
        qr[j*4+0] = t4.x; qr[j*4+1] = t4.y; qr[j*4+2] = t4.z; qr[j*4+3] = t4.w;
    }
    int cand[8]; int nc = 0;
    int pot[7];  int np = 0;
    if (g == 2) pot[np++] = 0;
    pot[np++] = qi-2; pot[np++] = qi-1; pot[np++] = qi; pot[np++] = qi+1; pot[np++] = qi+2;
    if (g == 2) pot[np++] = len-1;
    for (int i = 0; i < np; i++) {
        int kk = pot[i];
        if (kk < 0 || kk >= SS) continue;
        if (!adj_fn(g, qi, kk, len, sFlag)) continue;
        bool dup = false;
        for (int u = 0; u < nc; u++) if (cand[u] == kk) dup = true;
        if (!dup) cand[nc++] = kk;
    }
    const float scale = 0.17677669529663687f;
    float lg[8];
    float m = -1e30f;
    for (int i = 0; i < nc; i++) {
        const float* kp = basep + (size_t)cand[i]*QKVW + 256;
        float dot = 0.0f;
#pragma unroll
        for (int j = 0; j < 8; j++) {
            float4 k4 = *(const float4*)(kp + j*4);
            dot += qr[j*4+0]*k4.x + qr[j*4+1]*k4.y + qr[j*4+2]*k4.z + qr[j*4+3]*k4.w;
        }
        lg[i] = dot * scale;
        m = fmaxf(m, lg[i]);
    }
    float ssum = 0.0f;
    float o[32];
#pragma unroll
    for (int d = 0; d < 32; d++) o[d] = 0.0f;
    for (int i = 0; i < nc; i++) {
        float p = expf(lg[i] - m);
        ssum += p;
        const float* vp = basep + (size_t)cand[i]*QKVW + 512;
#pragma unroll
        for (int j = 0; j < 8; j++) {
            float4 v4 = *(const float4*)(vp + j*4);
            o[j*4+0] += p*v4.x; o[j*4+1] += p*v4.y; o[j*4+2] += p*v4.z; o[j*4+3] += p*v4.w;
        }
    }
    float inv = 1.0f / ssum;
#pragma unroll
    for (int j = 0; j < 8; j++) {
        float4 w4 = make_float4(o[j*4+0]*inv, o[j*4+1]*inv, o[j*4+2]*inv, o[j*4+3]*inv);
        *(float4*)(op + j*4) = w4;
    }
}

// ---------------- BN normalize (stats computed inline from sums) --------------
__global__ void __launch_bounds__(256) bn_norm_kernel(
    const float* __restrict__ in, float* __restrict__ outp,
    const float* __restrict__ gamma, const float* __restrict__ beta,
    const float* __restrict__ sums, int out_ld)
{
    int tid = threadIdx.x;
    int f = (tid & 63)*4;
    int t = blockIdx.x*4 + (tid >> 6);
    float4 s  = *(const float4*)&sums[f];
    float4 s2 = *(const float4*)&sums[EE + f];
    const float invN = 1.0f/(float)TT;
    float m0 = s.x*invN, m1 = s.y*invN, m2 = s.z*invN, m3 = s.w*invN;
    float r0 = rsqrtf(s2.x*invN - m0*m0 + 1e-5f);
    float r1 = rsqrtf(s2.y*invN - m1*m1 + 1e-5f);
    float r2 = rsqrtf(s2.z*invN - m2*m2 + 1e-5f);
    float r3 = rsqrtf(s2.w*invN - m3*m3 + 1e-5f);
    float4 v  = *(const float4*)&in[(size_t)t*EE + f];
    float4 gm = *(const float4*)&gamma[f];
    float4 bt = *(const float4*)&beta[f];
    float4 o;
    o.x = gm.x*(v.x - m0)*r0 + bt.x;
    o.y = gm.y*(v.y - m1)*r1 + bt.y;
    o.z = gm.z*(v.z - m2)*r2 + bt.z;
    o.w = gm.w*(v.w - m3)*r3 + bt.w;
    *(float4*)&outp[(size_t)t*out_ld + f] = o;
}

// ---------------- masked mean over S ----------------
__global__ void final_kernel(const float* __restrict__ mask, float* __restrict__ outp) {
    __shared__ float sM[SS];
    int b = blockIdx.x, e = threadIdx.x;
    sM[e] = mask[b*SS + e];
    __syncthreads();
    float acc = 0.0f;
    for (int s = 0; s < SS; s++) acc += g_xh[(size_t)(b*SS + s)*XHW + e]*sM[s];
    float denom = fmaxf((float)g_len[b], 1.0f);
    outp[b*EE + e] = acc/denom;
}

// ---------------- host orchestration (graph-capturable) ----------------
extern "C" void kernel_launch(void* const* d_in, const int* in_sizes, int n_in,
                              void* d_out, int out_size) {
    (void)in_sizes; (void)n_in; (void)out_size;
    const float* data = (const float*)d_in[0];
    const float* mask = (const float*)d_in[1];
    const float* Wc   = (const float*)d_in[2];
    const float* bc   = (const float*)d_in[3];
    const float* ftab = (const float*)d_in[4];
    const float* ptab = (const float*)d_in[5];
    const float* Wq   = (const float*)d_in[6];
    const float* Wk   = (const float*)d_in[7];
    const float* Wv   = (const float*)d_in[8];
    const float* Wo   = (const float*)d_in[9];
    const float* Wf   = (const float*)d_in[10];
    const float* bf   = (const float*)d_in[11];
    const float* g1   = (const float*)d_in[12];
    const float* b1   = (const float*)d_in[13];
    const float* Wff  = (const float*)d_in[14];
    const float* bff  = (const float*)d_in[15];
    const float* g2   = (const float*)d_in[16];
    const float* b2   = (const float*)d_in[17];
    float* outp = (float*)d_out;

    float *xh, *qkv, *h, *h2, *wqkv, *wf, *wff, *wcomb, *wbig, *sums;
    cudaGetSymbolAddress((void**)&xh,    g_xh);
    cudaGetSymbolAddress((void**)&qkv,   g_qkv);
    cudaGetSymbolAddress((void**)&h,     g_h);
    cudaGetSymbolAddress((void**)&h2,    g_h2);
    cudaGetSymbolAddress((void**)&wqkv,  g_wqkv);
    cudaGetSymbolAddress((void**)&wf,    g_wf);
    cudaGetSymbolAddress((void**)&wff,   g_wff);
    cudaGetSymbolAddress((void**)&wcomb, g_wcomb);
    cudaGetSymbolAddress((void**)&wbig,  g_wbig);
    cudaGetSymbolAddress((void**)&sums,  g_sums);

    cudaFuncSetAttribute(mma_gemm, cudaFuncAttributeMaxDynamicSharedMemorySize, GEMM_SMEM);

    // -------- weight precompute --------
    pack_w<<<(12*HH*EE*DKK)/256, 256>>>(Wq, Wk, Wv);
    round_copy<<<(LL*E3*EE)/256, 256>>>(Wf,  wf,  LL*E3*EE);
    round_copy<<<(LL*EE*EE)/256, 256>>>(Wff, wff, LL*EE*EE);
    // wcomb[z] = Wo[z] (256x256) @ wf block z (256x256), z = l*3+g
    mma_gemm<<<dim3(2, 2, 12), 256, GEMM_SMEM>>>(
        Wo, wf, wcomb, EE, EE, EE, EE, nullptr, nullptr, 0, 0,
        (size_t)EE*EE, (size_t)EE*EE, (size_t)EE*EE, nullptr);
    assemble_wbig<<<(LL*XHW*EE)/256, 256>>>(Wf);

    // -------- activations --------
    flags_kernel<<<BB, SS>>>(data, mask);
    embed_kernel<<<TT, EE>>>(data, Wc, bc, ftab, ptab);

    for (int l = 0; l < LL; l++) {
        // qkv: xh[:, :256] @ wqkv[l]  -> (TT, 2304)
        mma_gemm<<<dim3(QKVW/128, TT/128, 1), 256, GEMM_SMEM>>>(
            xh, wqkv + (size_t)l*EE*QKVW, qkv,
            EE, XHW, QKVW, QKVW, nullptr, nullptr, 0, 0, 0, 0, 0, nullptr);
        attn_kernel<<<dim3(BB, HH, 3), 256>>>(qkv, xh);
        // h = [x | heads] @ wbig[l] + bf[l]  (K=1024, stats fused)
        cudaMemsetAsync(sums, 0, 2*EE*sizeof(float), 0);
        mma_gemm<<<dim3(EE/128, TT/128, 1), 256, GEMM_SMEM>>>(
            xh, wbig + (size_t)l*XHW*EE, h,
            XHW, XHW, EE, EE, bf + l*EE, nullptr, 0, 0, 0, 0, 0, sums);
        bn_norm_kernel<<<TT/4, 256>>>(h, h, g1 + l*EE, b1 + l*EE, sums, EE);
        // h2 = h + relu(h @ Wff[l] + bff[l])  (stats fused)
        cudaMemsetAsync(sums, 0, 2*EE*sizeof(float), 0);
        mma_gemm<<<dim3(EE/128, TT/128, 1), 256, GEMM_SMEM>>>(
            h, wff + (size_t)l*EE*EE, h2,
            EE, EE, EE, EE, bff + l*EE, h, EE, 1, 0, 0, 0, sums);
        bn_norm_kernel<<<TT/4, 256>>>(h2, xh, g2 + l*EE, b2 + l*EE, sums, XHW);
    }
    final_kernel<<<BB, EE>>>(mask, outp);
}

// round 12
// speedup vs baseline: 5.3418x; 1.0281x over previous
#include <cuda_runtime.h>

#define BB 32
#define SS 256
#define EE 256
#define HH 8
#define DKK 32
#define LL 4
#define TT (BB*SS)
#define E3 (3*EE)
#define QKVW 2304
#define XHW 1024

__device__ float g_xh[TT*XHW];
__device__ float g_qkv[TT*QKVW];
__device__ float g_h[TT*EE];
__device__ float g_h2[TT*EE];
__device__ float g_wqkv[LL*EE*QKVW];
__device__ float g_wf[LL*E3*EE];
__device__ float g_wff[LL*EE*EE];
__device__ float g_woR[12*EE*EE];
__device__ float g_wcomb[12*EE*EE];
__device__ float g_wbig[LL*XHW*EE];
__device__ int   g_flag[TT];
__device__ int   g_len[BB];
__device__ float g_sums[2*EE];

__device__ __forceinline__ unsigned f2tf(float x) {
    unsigned r; asm("cvt.rna.tf32.f32 %0, %1;" : "=r"(r) : "f"(x)); return r;
}
__device__ __forceinline__ float rtf(float x) { return __uint_as_float(f2tf(x)); }

__global__ void pack_w(const float* __restrict__ Wq, const float* __restrict__ Wk,
                       const float* __restrict__ Wv) {
    int id = blockIdx.x*blockDim.x + threadIdx.x;
    int d  = id % DKK;
    int e  = (id / DKK) % EE;
    int h  = (id / (DKK*EE)) % HH;
    int lg = id / (DKK*EE*HH);
    int l = lg / 3, g = lg % 3;
    size_t dst = ((size_t)l*EE + e)*QKVW + g*768 + h*DKK + d;
    g_wqkv[dst +   0] = rtf(Wq[id]);
    g_wqkv[dst + 256] = rtf(Wk[id]);
    g_wqkv[dst + 512] = rtf(Wv[id]);
}
__global__ void round_copy(const float* __restrict__ s, float* __restrict__ d, int n) {
    int i = blockIdx.x*blockDim.x + threadIdx.x;
    if (i < n) d[i] = rtf(s[i]);
}
__global__ void assemble_wbig(const float* __restrict__ Wf) {
    int id = blockIdx.x*blockDim.x + threadIdx.x;   // LL*XHW*EE
    int n = id % EE;
    int row = (id / EE) % XHW;
    int l = id / (EE*XHW);
    float v;
    if (row < 256) {
        const float* wf = Wf + (size_t)l*E3*EE;
        v = wf[(size_t)row*EE + n] + wf[(size_t)(256+row)*EE + n] + wf[(size_t)(512+row)*EE + n];
    } else {
        int g = (row - 256) >> 8, j = (row - 256) & 255;
        v = g_wcomb[(size_t)(l*3 + g)*EE*EE + (size_t)j*EE + n];
    }
    g_wbig[id] = rtf(v);
}

__global__ void flags_kernel(const float* __restrict__ data, const float* __restrict__ mask) {
    int b = blockIdx.x, s = threadIdx.x;
    int idx = b*SS + s;
    float mk = mask[idx];
    float p1 = data[idx*5+2], p2 = data[idx*5+3], p3 = data[idx*5+4];
    int f = 0;
    if (p1 == 1.0f) f = 100;
    if (p2 == 1.0f || p3 == 1.0f) f = 101;
    if (mk == 0.0f) f = 102;
    g_flag[idx] = f;
    __shared__ float red[SS];
    red[s] = mk;
    __syncthreads();
    for (int st = 128; st > 0; st >>= 1) {
        if (s < st) red[s] += red[s+st];
        __syncthreads();
    }
    if (s == 0) g_len[b] = (int)(red[0] + 0.5f);
}

__global__ void embed_kernel(const float* __restrict__ data, const float* __restrict__ Wc,
                             const float* __restrict__ bc, const float* __restrict__ ftab,
                             const float* __restrict__ ptab) {
    int t = blockIdx.x, e = threadIdx.x;
    float c0 = data[t*5+0], c1 = data[t*5+1];
    int fl = g_flag[t];
    int s = t & (SS-1);
    g_xh[(size_t)t*XHW + e] = rtf(c0*Wc[e] + c1*Wc[EE+e] + bc[e] + ftab[fl*EE+e] + ptab[s*EE+e]);
}

// ---- tf32 mma.sync GEMM, cp.async double-buffered; A and B both pre-rounded ----
__device__ __forceinline__ void cpasync16(float* dst, const float* src) {
    unsigned s = (unsigned)__cvta_generic_to_shared(dst);
    asm volatile("cp.async.cg.shared.global [%0], [%1], 16;" :: "r"(s), "l"(src));
}
#define SA_ST 36
#define SB_ST 136
#define TILE_A_W (128*SA_ST)
#define TILE_B_W (32*SB_ST)
#define BUF_W (TILE_A_W + TILE_B_W)
#define GEMM_SMEM (2*BUF_W*4)

__device__ __forceinline__ void load_tile(float* bufA, float* bufB,
        const float* A, const float* Bm, int lda, int ldb,
        int m0, int n0, int k0, int tid)
{
    {
        int row = tid >> 1, c = (tid & 1)*16;
        const float* src = A + (size_t)(m0 + row)*lda + k0 + c;
        float* dst = bufA + row*SA_ST + c;
        cpasync16(dst,      src);
        cpasync16(dst + 4,  src + 4);
        cpasync16(dst + 8,  src + 8);
        cpasync16(dst + 12, src + 12);
    }
    {
        int krow = tid >> 3, c = (tid & 7)*16;
        const float* src = Bm + (size_t)(k0 + krow)*ldb + n0 + c;
        float* dst = bufB + krow*SB_ST + c;
        cpasync16(dst,      src);
        cpasync16(dst + 4,  src + 4);
        cpasync16(dst + 8,  src + 8);
        cpasync16(dst + 12, src + 12);
    }
    asm volatile("cp.async.commit_group;");
}

__global__ void __launch_bounds__(256, 2) mma_gemm(
    const float* __restrict__ A, const float* __restrict__ Bm, float* __restrict__ C,
    int K, int lda, int ldb, int ldc,
    const float* __restrict__ bias, const float* __restrict__ resid, int ldr, int relu,
    size_t batchA, size_t batchB, size_t batchC, float* stats)
{
    extern __shared__ float smem[];
    int z = blockIdx.z;
    A  += (size_t)z*batchA; Bm += (size_t)z*batchB; C += (size_t)z*batchC;
    int tid = threadIdx.x, lane = tid & 31, warp = tid >> 5;
    int wm = warp & 1, wn = warp >> 1;
    int m0 = blockIdx.y*128, n0 = blockIdx.x*128;
    float acc[4][4][4];
#pragma unroll
    for (int a2 = 0; a2 < 4; a2++)
#pragma unroll
        for (int b2 = 0; b2 < 4; b2++)
#pragma unroll
            for (int c2 = 0; c2 < 4; c2++) acc[a2][b2][c2] = 0.0f;

    int nk = K >> 5;
    load_tile(smem, smem + TILE_A_W, A, Bm, lda, ldb, m0, n0, 0, tid);

    for (int it = 0; it < nk; it++) {
        asm volatile("cp.async.wait_group 0;");
        __syncthreads();
        int cur = it & 1;
        if (it + 1 < nk)
            load_tile(smem + (cur^1)*BUF_W, smem + (cur^1)*BUF_W + TILE_A_W,
                      A, Bm, lda, ldb, m0, n0, (it+1)*32, tid);
        const unsigned* sA = (const unsigned*)(smem + cur*BUF_W);
        const unsigned* sB = sA + TILE_A_W;
#pragma unroll
        for (int kk = 0; kk < 4; kk++) {
            int kb = kk*8;
            unsigned af[4][4], bf[4][2];
#pragma unroll
            for (int mt = 0; mt < 4; mt++) {
                int r = wm*64 + mt*16 + (lane >> 2);
                int kc = kb + (lane & 3);
                af[mt][0] = sA[r*SA_ST + kc];
                af[mt][1] = sA[(r+8)*SA_ST + kc];
                af[mt][2] = sA[r*SA_ST + kc + 4];
                af[mt][3] = sA[(r+8)*SA_ST + kc + 4];
            }
#pragma unroll
            for (int nt = 0; nt < 4; nt++) {
                int c = wn*32 + nt*8 + (lane >> 2);
                int kr = kb + (lane & 3);
                bf[nt][0] = sB[kr*SB_ST + c];
                bf[nt][1] = sB[(kr+4)*SB_ST + c];
            }
#pragma unroll
            for (int mt = 0; mt < 4; mt++)
#pragma unroll
                for (int nt = 0; nt < 4; nt++)
                    asm volatile(
                        "mma.sync.aligned.m16n8k8.row.col.f32.tf32.tf32.f32 "
                        "{%0,%1,%2,%3}, {%4,%5,%6,%7}, {%8,%9}, {%0,%1,%2,%3};"
                        : "+f"(acc[mt][nt][0]), "+f"(acc[mt][nt][1]),
                          "+f"(acc[mt][nt][2]), "+f"(acc[mt][nt][3])
                        : "r"(af[mt][0]), "r"(af[mt][1]), "r"(af[mt][2]), "r"(af[mt][3]),
                          "r"(bf[nt][0]), "r"(bf[nt][1]));
        }
    }
    float cs[4][2] = {}, cs2[4][2] = {};
#pragma unroll
    for (int mt = 0; mt < 4; mt++) {
#pragma unroll
        for (int nt = 0; nt < 4; nt++) {
            int r = m0 + wm*64 + mt*16 + (lane >> 2);
            int c = n0 + wn*32 + nt*8 + (lane & 3)*2;
#pragma unroll
            for (int half = 0; half < 2; half++) {
                int rr = r + half*8;
                float v0 = acc[mt][nt][half*2+0];
                float v1 = acc[mt][nt][half*2+1];
                if (bias)  { v0 += bias[c];  v1 += bias[c+1]; }
                if (relu)  { v0 = fmaxf(v0, 0.0f); v1 = fmaxf(v1, 0.0f); }
                if (resid) {
                    float2 rv = *(const float2*)&resid[(size_t)rr*ldr + c];
                    v0 += rv.x; v1 += rv.y;
                }
                *(float2*)&C[(size_t)rr*ldc + c] = make_float2(v0, v1);
                if (stats) {
                    cs[nt][0]  += v0;    cs[nt][1]  += v1;
                    cs2[nt][0] += v0*v0; cs2[nt][1] += v1*v1;
                }
            }
        }
    }
    if (stats) {
        float* red = smem;
        __syncthreads();
        if (tid < 256) red[tid] = 0.0f;
        __syncthreads();
#pragma unroll
        for (int nt = 0; nt < 4; nt++) {
#pragma unroll
            for (int j = 0; j < 2; j++) {
                float s = cs[nt][j], s2 = cs2[nt][j];
#pragma unroll
                for (int o = 16; o >= 4; o >>= 1) {
                    s  += __shfl_xor_sync(0xffffffffu, s,  o);
                    s2 += __shfl_xor_sync(0xffffffffu, s2, o);
                }
                if ((lane >> 2) == 0) {
                    int cc = wn*32 + nt*8 + (lane & 3)*2 + j;
                    atomicAdd(&red[cc], s);
                    atomicAdd(&red[128 + cc], s2);
                }
            }
        }
        __syncthreads();
        if (tid < 128) {
            atomicAdd(&stats[n0 + tid],      red[tid]);
            atomicAdd(&stats[EE + n0 + tid], red[128 + tid]);
        }
    }
}

__device__ __forceinline__ bool adj_fn(int g, int q, int k, int len, const int* fl) {
    if (q == k) return q < len;
    if (g == 0) {
        if (k == q+1) return fl[q] == 100 && q < len-1;
        if (q == k+1) return fl[k] == 100 && k < len-1;
        return false;
    } else if (g == 1) {
        if (k == q+1) return fl[q] == 100 && q < len-1;
        if (q == k+1) return fl[k] == 100 && k < len-1;
        if (k == q+2) return fl[q] == 100 && fl[q+1] == 100 && q < len-2;
        if (q == k+2) return fl[k] == 100 && fl[k+1] == 100 && k < len-2;
        return false;
    } else {
        if (q == 0 && k == len-1 && len > 1) return true;
        if (k == 0 && q == len-1 && len > 1) return true;
        if (k == q+1) return fl[q] == 101 && q < len-1;
        if (q == k+1) return fl[k] == 101 && k < len-1;
        return false;
    }
}

__global__ void __launch_bounds__(256) attn_kernel(
    const float* __restrict__ qkv, float* __restrict__ xh)
{
    __shared__ float sPart[8][32];
    __shared__ float sVmean[32];
    __shared__ int   sFlag[SS];
    __shared__ int   sLenS;
    int b = blockIdx.x, h = blockIdx.y, g = blockIdx.z;
    int tid = threadIdx.x;
    const float* basep = qkv + (size_t)b*SS*QKVW + g*768 + h*DKK;
    {
        int d = tid & 31, ch = tid >> 5;
        float s = 0.0f;
        for (int r = ch*32; r < ch*32 + 32; r++)
            s += basep[(size_t)r*QKVW + 512 + d];
        sPart[ch][d] = s;
    }
    sFlag[tid] = g_flag[b*SS + tid];
    if (tid == 0) sLenS = g_len[b];
    __syncthreads();
    if (tid < 32) {
        float s = 0.0f;
#pragma unroll
        for (int c2 = 0; c2 < 8; c2++) s += sPart[c2][tid];
        sVmean[tid] = rtf(s * (1.0f/256.0f));
    }
    __syncthreads();
    int qi = tid, len = sLenS;
    float* op = xh + (size_t)(b*SS + qi)*XHW + 256 + g*256 + h*DKK;
    if (qi >= len) {
#pragma unroll
        for (int j = 0; j < 8; j++)
            *(float4*)(op + j*4) = *(float4*)(&sVmean[j*4]);
        return;
    }
    float qr[32];
    const float* qp = basep + (size_t)qi*QKVW;
#pragma unroll
    for (int j = 0; j < 8; j++) {
        float4 t4 = *(const float4*)(qp + j*4);
        qr[j*4+0] = t4.x; qr[j*4+1] = t4.y; qr[j*4+2] = t4.z; qr[j*4+3] = t4.w;
    }
    int cand[8]; int nc = 0;
    int pot[7];  int np = 0;
    if (g == 2) pot[np++] = 0;
    pot[np++] = qi-2; pot[np++] = qi-1; pot[np++] = qi; pot[np++] = qi+1; pot[np++] = qi+2;
    if (g == 2) pot[np++] = len-1;
    for (int i = 0; i < np; i++) {
        int kk = pot[i];
        if (kk < 0 || kk >= SS) continue;
        if (!adj_fn(g, qi, kk, len, sFlag)) continue;
        bool dup = false;
        for (int u = 0; u < nc; u++) if (cand[u] == kk) dup = true;
        if (!dup) cand[nc++] = kk;
    }
    const float scale = 0.17677669529663687f;
    float lg[8];
    float m = -1e30f;
    for (int i = 0; i < nc; i++) {
        const float* kp = basep + (size_t)cand[i]*QKVW + 256;
        float dot = 0.0f;
#pragma unroll
        for (int j = 0; j < 8; j++) {
            float4 k4 = *(const float4*)(kp + j*4);
            dot += qr[j*4+0]*k4.x + qr[j*4+1]*k4.y + qr[j*4+2]*k4.z + qr[j*4+3]*k4.w;
        }
        lg[i] = dot * scale;
        m = fmaxf(m, lg[i]);
    }
    float ssum = 0.0f;
    float o[32];
#pragma unroll
    for (int d = 0; d < 32; d++) o[d] = 0.0f;
    for (int i = 0; i < nc; i++) {
        float p = __expf(lg[i] - m);
        ssum += p;
        const float* vp = basep + (size_t)cand[i]*QKVW + 512;
#pragma unroll
        for (int j = 0; j < 8; j++) {
            float4 v4 = *(const float4*)(vp + j*4);
            o[j*4+0] += p*v4.x; o[j*4+1] += p*v4.y; o[j*4+2] += p*v4.z; o[j*4+3] += p*v4.w;
        }
    }
    float inv = 1.0f / ssum;
#pragma unroll
    for (int j = 0; j < 8; j++) {
        float4 w4 = make_float4(rtf(o[j*4+0]*inv), rtf(o[j*4+1]*inv),
                                rtf(o[j*4+2]*inv), rtf(o[j*4+3]*inv));
        *(float4*)(op + j*4) = w4;
    }
}

__global__ void __launch_bounds__(256) bn_norm_kernel(
    const float* __restrict__ in, float* __restrict__ outp,
    const float* __restrict__ gamma, const float* __restrict__ beta,
    const float* __restrict__ sums, int out_ld)
{
    int tid = threadIdx.x;
    int f = (tid & 63)*4;
    int t = blockIdx.x*4 + (tid >> 6);
    float4 s  = *(const float4*)&sums[f];
    float4 s2 = *(const float4*)&sums[EE + f];
    const float invN = 1.0f/(float)TT;
    float m0 = s.x*invN, m1 = s.y*invN, m2 = s.z*invN, m3 = s.w*invN;
    float r0 = rsqrtf(s2.x*invN - m0*m0 + 1e-5f);
    float r1 = rsqrtf(s2.y*invN - m1*m1 + 1e-5f);
    float r2 = rsqrtf(s2.z*invN - m2*m2 + 1e-5f);
    float r3 = rsqrtf(s2.w*invN - m3*m3 + 1e-5f);
    float4 v  = *(const float4*)&in[(size_t)t*EE + f];
    float4 gm = *(const float4*)&gamma[f];
    float4 bt = *(const float4*)&beta[f];
    float4 o;
    o.x = rtf(gm.x*(v.x - m0)*r0 + bt.x);
    o.y = rtf(gm.y*(v.y - m1)*r1 + bt.y);
    o.z = rtf(gm.z*(v.z - m2)*r2 + bt.z);
    o.w = rtf(gm.w*(v.w - m3)*r3 + bt.w);
    *(float4*)&outp[(size_t)t*out_ld + f] = o;
}

__global__ void final_kernel(const float* __restrict__ mask, float* __restrict__ outp) {
    __shared__ float sM[SS];
    int b = blockIdx.x, e = threadIdx.x;
    sM[e] = mask[b*SS + e];
    __syncthreads();
    float acc = 0.0f;
    for (int s = 0; s < SS; s++) acc += g_xh[(size_t)(b*SS + s)*XHW + e]*sM[s];
    float denom = fmaxf((float)g_len[b], 1.0f);
    outp[b*EE + e] = acc/denom;
}

extern "C" void kernel_launch(void* const* d_in, const int* in_sizes, int n_in,
                              void* d_out, int out_size) {
    (void)in_sizes; (void)n_in; (void)out_size;
    const float* data = (const float*)d_in[0];
    const float* mask = (const float*)d_in[1];
    const float* Wc   = (const float*)d_in[2];
    const float* bc   = (const float*)d_in[3];
    const float* ftab = (const float*)d_in[4];
    const float* ptab = (const float*)d_in[5];
    const float* Wq   = (const float*)d_in[6];
    const float* Wk   = (const float*)d_in[7];
    const float* Wv   = (const float*)d_in[8];
    const float* Wo   = (const float*)d_in[9];
    const float* Wf   = (const float*)d_in[10];
    const float* bf   = (const float*)d_in[11];
    const float* g1   = (const float*)d_in[12];
    const float* b1   = (const float*)d_in[13];
    const float* Wff  = (const float*)d_in[14];
    const float* bff  = (const float*)d_in[15];
    const float* g2   = (const float*)d_in[16];
    const float* b2   = (const float*)d_in[17];
    float* outp = (float*)d_out;

    float *xh, *qkv, *h, *h2, *wqkv, *wf, *wff, *woR, *wcomb, *wbig, *sums;
    cudaGetSymbolAddress((void**)&xh,    g_xh);
    cudaGetSymbolAddress((void**)&qkv,   g_qkv);
    cudaGetSymbolAddress((void**)&h,     g_h);
    cudaGetSymbolAddress((void**)&h2,    g_h2);
    cudaGetSymbolAddress((void**)&wqkv,  g_wqkv);
    cudaGetSymbolAddress((void**)&wf,    g_wf);
    cudaGetSymbolAddress((void**)&wff,   g_wff);
    cudaGetSymbolAddress((void**)&woR,   g_woR);
    cudaGetSymbolAddress((void**)&wcomb, g_wcomb);
    cudaGetSymbolAddress((void**)&wbig,  g_wbig);
    cudaGetSymbolAddress((void**)&sums,  g_sums);

    cudaFuncSetAttribute(mma_gemm, cudaFuncAttributeMaxDynamicSharedMemorySize, GEMM_SMEM);

    pack_w<<<(12*HH*EE*DKK)/256, 256>>>(Wq, Wk, Wv);
    round_copy<<<(12*EE*EE)/256, 256>>>(Wo,  woR, 12*EE*EE);
    round_copy<<<(LL*E3*EE)/256, 256>>>(Wf,  wf,  LL*E3*EE);
    round_copy<<<(LL*EE*EE)/256, 256>>>(Wff, wff, LL*EE*EE);
    mma_gemm<<<dim3(2, 2, 12), 256, GEMM_SMEM>>>(
        woR, wf, wcomb, EE, EE, EE, EE, nullptr, nullptr, 0, 0,
        (size_t)EE*EE, (size_t)EE*EE, (size_t)EE*EE, nullptr);
    assemble_wbig<<<(LL*XHW*EE)/256, 256>>>(Wf);

    flags_kernel<<<BB, SS>>>(data, mask);
    embed_kernel<<<TT, EE>>>(data, Wc, bc, ftab, ptab);

    for (int l = 0; l < LL; l++) {
        mma_gemm<<<dim3(QKVW/128, TT/128, 1), 256, GEMM_SMEM>>>(
            xh, wqkv + (size_t)l*EE*QKVW, qkv,
            EE, XHW, QKVW, QKVW, nullptr, nullptr, 0, 0, 0, 0, 0, nullptr);
        attn_kernel<<<dim3(BB, HH, 3), 256>>>(qkv, xh);
        cudaMemsetAsync(sums, 0, 2*EE*sizeof(float), 0);
        mma_gemm<<<dim3(EE/128, TT/128, 1), 256, GEMM_SMEM>>>(
            xh, wbig + (size_t)l*XHW*EE, h,
            XHW, XHW, EE, EE, bf + l*EE, nullptr, 0, 0, 0, 0, 0, sums);
        bn_norm_kernel<<<TT/4, 256>>>(h, h, g1 + l*EE, b1 + l*EE, sums, EE);
        cudaMemsetAsync(sums, 0, 2*EE*sizeof(float), 0);
        mma_gemm<<<dim3(EE/128, TT/128, 1), 256, GEMM_SMEM>>>(
            h, wff + (size_t)l*EE*EE, h2,
            EE, EE, EE, EE, bff + l*EE, h, EE, 1, 0, 0, 0, sums);
        bn_norm_kernel<<<TT/4, 256>>>(h2, xh, g2 + l*EE, b2 + l*EE, sums, XHW);
    }
    final_kernel<<<BB, EE>>>(mask, outp);
}

// round 13
// speedup vs baseline: 5.3421x; 1.0001x over previous
#include <cuda_runtime.h>

#define BB 32
#define SS 256
#define EE 256
#define HH 8
#define DKK 32
#define LL 4
#define TT (BB*SS)
#define E3 (3*EE)
#define QKVW 2304
#define XHW 1024

__device__ float g_xh[TT*XHW];
__device__ float g_qkv[TT*QKVW];
__device__ float g_h[TT*EE];
__device__ float g_h2[TT*EE];
__device__ float g_wqkv[LL*EE*QKVW];
__device__ float g_wf[LL*E3*EE];
__device__ float g_wff[LL*EE*EE];
__device__ float g_woR[12*EE*EE];
__device__ float g_wcomb[12*EE*EE];
__device__ float g_wbig[LL*XHW*EE];
__device__ int   g_flag[TT];
__device__ int   g_len[BB];
__device__ float g_sums[2*EE];

__device__ __forceinline__ unsigned f2tf(float x) {
    unsigned r; asm("cvt.rna.tf32.f32 %0, %1;" : "=r"(r) : "f"(x)); return r;
}
__device__ __forceinline__ float rtf(float x) { return __uint_as_float(f2tf(x)); }

__global__ void pack_w(const float* __restrict__ Wq, const float* __restrict__ Wk,
                       const float* __restrict__ Wv) {
    int id = blockIdx.x*blockDim.x + threadIdx.x;
    int d  = id % DKK;
    int e  = (id / DKK) % EE;
    int h  = (id / (DKK*EE)) % HH;
    int lg = id / (DKK*EE*HH);
    int l = lg / 3, g = lg % 3;
    size_t dst = ((size_t)l*EE + e)*QKVW + g*768 + h*DKK + d;
    g_wqkv[dst +   0] = rtf(Wq[id]);
    g_wqkv[dst + 256] = rtf(Wk[id]);
    g_wqkv[dst + 512] = rtf(Wv[id]);
}
__global__ void round_copy(const float* __restrict__ s, float* __restrict__ d, int n) {
    int i = blockIdx.x*blockDim.x + threadIdx.x;
    if (i < n) d[i] = rtf(s[i]);
}
__global__ void assemble_wbig(const float* __restrict__ Wf) {
    int id = blockIdx.x*blockDim.x + threadIdx.x;   // LL*XHW*EE
    int n = id % EE;
    int row = (id / EE) % XHW;
    int l = id / (EE*XHW);
    float v;
    if (row < 256) {
        const float* wf = Wf + (size_t)l*E3*EE;
        v = wf[(size_t)row*EE + n] + wf[(size_t)(256+row)*EE + n] + wf[(size_t)(512+row)*EE + n];
    } else {
        int g = (row - 256) >> 8, j = (row - 256) & 255;
        v = g_wcomb[(size_t)(l*3 + g)*EE*EE + (size_t)j*EE + n];
    }
    g_wbig[id] = rtf(v);
}

__global__ void flags_kernel(const float* __restrict__ data, const float* __restrict__ mask) {
    int b = blockIdx.x, s = threadIdx.x;
    int idx = b*SS + s;
    float mk = mask[idx];
    float p1 = data[idx*5+2], p2 = data[idx*5+3], p3 = data[idx*5+4];
    int f = 0;
    if (p1 == 1.0f) f = 100;
    if (p2 == 1.0f || p3 == 1.0f) f = 101;
    if (mk == 0.0f) f = 102;
    g_flag[idx] = f;
    __shared__ float red[SS];
    red[s] = mk;
    __syncthreads();
    for (int st = 128; st > 0; st >>= 1) {
        if (s < st) red[s] += red[s+st];
        __syncthreads();
    }
    if (s == 0) g_len[b] = (int)(red[0] + 0.5f);
}

__global__ void embed_kernel(const float* __restrict__ data, const float* __restrict__ Wc,
                             const float* __restrict__ bc, const float* __restrict__ ftab,
                             const float* __restrict__ ptab) {
    int t = blockIdx.x, e = threadIdx.x;
    float c0 = data[t*5+0], c1 = data[t*5+1];
    int fl = g_flag[t];
    int s = t & (SS-1);
    g_xh[(size_t)t*XHW + e] = rtf(c0*Wc[e] + c1*Wc[EE+e] + bc[e] + ftab[fl*EE+e] + ptab[s*EE+e]);
}

// ---- tf32 mma.sync GEMM, 3-stage cp.async ring; A and B pre-rounded ----
__device__ __forceinline__ void cpasync16(float* dst, const float* src) {
    unsigned s = (unsigned)__cvta_generic_to_shared(dst);
    asm volatile("cp.async.cg.shared.global [%0], [%1], 16;" :: "r"(s), "l"(src));
}
#define SA_ST 36
#define SB_ST 136
#define TILE_A_W (128*SA_ST)
#define TILE_B_W (32*SB_ST)
#define BUF_W (TILE_A_W + TILE_B_W)
#define GEMM_SMEM (3*BUF_W*4)       // 107520 B: 3 stages, 2 CTAs/SM = 210 KB

__device__ __forceinline__ void load_tile(float* bufA, float* bufB,
        const float* A, const float* Bm, int lda, int ldb,
        int m0, int n0, int k0, int tid)
{
    {
        int row = tid >> 1, c = (tid & 1)*16;
        const float* src = A + (size_t)(m0 + row)*lda + k0 + c;
        float* dst = bufA + row*SA_ST + c;
        cpasync16(dst,      src);
        cpasync16(dst + 4,  src + 4);
        cpasync16(dst + 8,  src + 8);
        cpasync16(dst + 12, src + 12);
    }
    {
        int krow = tid >> 3, c = (tid & 7)*16;
        const float* src = Bm + (size_t)(k0 + krow)*ldb + n0 + c;
        float* dst = bufB + krow*SB_ST + c;
        cpasync16(dst,      src);
        cpasync16(dst + 4,  src + 4);
        cpasync16(dst + 8,  src + 8);
        cpasync16(dst + 12, src + 12);
    }
    asm volatile("cp.async.commit_group;");
}

__global__ void __launch_bounds__(256, 2) mma_gemm(
    const float* __restrict__ A, const float* __restrict__ Bm, float* __restrict__ C,
    int K, int lda, int ldb, int ldc,
    const float* __restrict__ bias, const float* __restrict__ resid, int ldr, int relu,
    size_t batchA, size_t batchB, size_t batchC, float* stats)
{
    extern __shared__ float smem[];
    int z = blockIdx.z;
    A  += (size_t)z*batchA; Bm += (size_t)z*batchB; C += (size_t)z*batchC;
    int tid = threadIdx.x, lane = tid & 31, warp = tid >> 5;
    int wm = warp & 1, wn = warp >> 1;
    int m0 = blockIdx.y*128, n0 = blockIdx.x*128;
    float acc[4][4][4];
#pragma unroll
    for (int a2 = 0; a2 < 4; a2++)
#pragma unroll
        for (int b2 = 0; b2 < 4; b2++)
#pragma unroll
            for (int c2 = 0; c2 < 4; c2++) acc[a2][b2][c2] = 0.0f;

    int nk = K >> 5;   // always >= 8 here
    load_tile(smem,          smem + TILE_A_W,          A, Bm, lda, ldb, m0, n0, 0,  tid);
    load_tile(smem + BUF_W,  smem + BUF_W + TILE_A_W,  A, Bm, lda, ldb, m0, n0, 32, tid);

    int cur = 0, nxt = 2;   // buffer index of tile it, and of tile it+2
    for (int it = 0; it < nk; it++) {
        if (it + 2 < nk) asm volatile("cp.async.wait_group 1;");
        else             asm volatile("cp.async.wait_group 0;");
        __syncthreads();
        if (it + 2 < nk) {
            load_tile(smem + nxt*BUF_W, smem + nxt*BUF_W + TILE_A_W,
                      A, Bm, lda, ldb, m0, n0, (it+2)*32, tid);
        }
        const unsigned* sA = (const unsigned*)(smem + cur*BUF_W);
        const unsigned* sB = sA + TILE_A_W;
#pragma unroll
        for (int kk = 0; kk < 4; kk++) {
            int kb = kk*8;
            unsigned af[4][4], bf[4][2];
#pragma unroll
            for (int mt = 0; mt < 4; mt++) {
                int r = wm*64 + mt*16 + (lane >> 2);
                int kc = kb + (lane & 3);
                af[mt][0] = sA[r*SA_ST + kc];
                af[mt][1] = sA[(r+8)*SA_ST + kc];
                af[mt][2] = sA[r*SA_ST + kc + 4];
                af[mt][3] = sA[(r+8)*SA_ST + kc + 4];
            }
#pragma unroll
            for (int nt = 0; nt < 4; nt++) {
                int c = wn*32 + nt*8 + (lane >> 2);
                int kr = kb + (lane & 3);
                bf[nt][0] = sB[kr*SB_ST + c];
                bf[nt][1] = sB[(kr+4)*SB_ST + c];
            }
#pragma unroll
            for (int mt = 0; mt < 4; mt++)
#pragma unroll
                for (int nt = 0; nt < 4; nt++)
                    asm volatile(
                        "mma.sync.aligned.m16n8k8.row.col.f32.tf32.tf32.f32 "
                        "{%0,%1,%2,%3}, {%4,%5,%6,%7}, {%8,%9}, {%0,%1,%2,%3};"
                        : "+f"(acc[mt][nt][0]), "+f"(acc[mt][nt][1]),
                          "+f"(acc[mt][nt][2]), "+f"(acc[mt][nt][3])
                        : "r"(af[mt][0]), "r"(af[mt][1]), "r"(af[mt][2]), "r"(af[mt][3]),
                          "r"(bf[nt][0]), "r"(bf[nt][1]));
        }
        cur = cur == 2 ? 0 : cur + 1;
        nxt = nxt == 2 ? 0 : nxt + 1;
    }
    float cs[4][2] = {}, cs2[4][2] = {};
#pragma unroll
    for (int mt = 0; mt < 4; mt++) {
#pragma unroll
        for (int nt = 0; nt < 4; nt++) {
            int r = m0 + wm*64 + mt*16 + (lane >> 2);
            int c = n0 + wn*32 + nt*8 + (lane & 3)*2;
#pragma unroll
            for (int half = 0; half < 2; half++) {
                int rr = r + half*8;
                float v0 = acc[mt][nt][half*2+0];
                float v1 = acc[mt][nt][half*2+1];
                if (bias)  { v0 += bias[c];  v1 += bias[c+1]; }
                if (relu)  { v0 = fmaxf(v0, 0.0f); v1 = fmaxf(v1, 0.0f); }
                if (resid) {
                    float2 rv = *(const float2*)&resid[(size_t)rr*ldr + c];
                    v0 += rv.x; v1 += rv.y;
                }
                *(float2*)&C[(size_t)rr*ldc + c] = make_float2(v0, v1);
                if (stats) {
                    cs[nt][0]  += v0;    cs[nt][1]  += v1;
                    cs2[nt][0] += v0*v0; cs2[nt][1] += v1*v1;
                }
            }
        }
    }
    if (stats) {
        float* red = smem;
        __syncthreads();
        if (tid < 256) red[tid] = 0.0f;
        __syncthreads();
#pragma unroll
        for (int nt = 0; nt < 4; nt++) {
#pragma unroll
            for (int j = 0; j < 2; j++) {
                float s = cs[nt][j], s2 = cs2[nt][j];
#pragma unroll
                for (int o = 16; o >= 4; o >>= 1) {
                    s  += __shfl_xor_sync(0xffffffffu, s,  o);
                    s2 += __shfl_xor_sync(0xffffffffu, s2, o);
                }
                if ((lane >> 2) == 0) {
                    int cc = wn*32 + nt*8 + (lane & 3)*2 + j;
                    atomicAdd(&red[cc], s);
                    atomicAdd(&red[128 + cc], s2);
                }
            }
        }
        __syncthreads();
        if (tid < 128) {
            atomicAdd(&stats[n0 + tid],      red[tid]);
            atomicAdd(&stats[EE + n0 + tid], red[128 + tid]);
        }
    }
}

__device__ __forceinline__ bool adj_fn(int g, int q, int k, int len, const int* fl) {
    if (q == k) return q < len;
    if (g == 0) {
        if (k == q+1) return fl[q] == 100 && q < len-1;
        if (q == k+1) return fl[k] == 100 && k < len-1;
        return false;
    } else if (g == 1) {
        if (k == q+1) return fl[q] == 100 && q < len-1;
        if (q == k+1) return fl[k] == 100 && k < len-1;
        if (k == q+2) return fl[q] == 100 && fl[q+1] == 100 && q < len-2;
        if (q == k+2) return fl[k] == 100 && fl[k+1] == 100 && k < len-2;
        return false;
    } else {
        if (q == 0 && k == len-1 && len > 1) return true;
        if (k == 0 && q == len-1 && len > 1) return true;
        if (k == q+1) return fl[q] == 101 && q < len-1;
        if (q == k+1) return fl[k] == 101 && k < len-1;
        return false;
    }
}

__global__ void __launch_bounds__(256) attn_kernel(
    const float* __restrict__ qkv, float* __restrict__ xh)
{
    __shared__ float sPart[8][32];
    __shared__ float sVmean[32];
    __shared__ int   sFlag[SS];
    __shared__ int   sLenS;
    int b = blockIdx.x, h = blockIdx.y, g = blockIdx.z;
    int tid = threadIdx.x;
    const float* basep = qkv + (size_t)b*SS*QKVW + g*768 + h*DKK;
    {
        int d = tid & 31, ch = tid >> 5;
        float s = 0.0f;
        for (int r = ch*32; r < ch*32 + 32; r++)
            s += basep[(size_t)r*QKVW + 512 + d];
        sPart[ch][d] = s;
    }
    sFlag[tid] = g_flag[b*SS + tid];
    if (tid == 0) sLenS = g_len[b];
    __syncthreads();
    if (tid < 32) {
        float s = 0.0f;
#pragma unroll
        for (int c2 = 0; c2 < 8; c2++) s += sPart[c2][tid];
        sVmean[tid] = rtf(s * (1.0f/256.0f));
    }
    __syncthreads();
    int qi = tid, len = sLenS;
    float* op = xh + (size_t)(b*SS + qi)*XHW + 256 + g*256 + h*DKK;
    if (qi >= len) {
#pragma unroll
        for (int j = 0; j < 8; j++)
            *(float4*)(op + j*4) = *(float4*)(&sVmean[j*4]);
        return;
    }
    float qr[32];
    const float* qp = basep + (size_t)qi*QKVW;
#pragma unroll
    for (int j = 0; j < 8; j++) {
        float4 t4 = *(const float4*)(qp + j*4);
        qr[j*4+0] = t4.x; qr[j*4+1] = t4.y; qr[j*4+2] = t4.z; qr[j*4+3] = t4.w;
    }
    int cand[8]; int nc = 0;
    int pot[7];  int np = 0;
    if (g == 2) pot[np++] = 0;
    pot[np++] = qi-2; pot[np++] = qi-1; pot[np++] = qi; pot[np++] = qi+1; pot[np++] = qi+2;
    if (g == 2) pot[np++] = len-1;
    for (int i = 0; i < np; i++) {
        int kk = pot[i];
        if (kk < 0 || kk >= SS) continue;
        if (!adj_fn(g, qi, kk, len, sFlag)) continue;
        bool dup = false;
        for (int u = 0; u < nc; u++) if (cand[u] == kk) dup = true;
        if (!dup) cand[nc++] = kk;
    }
    const float scale = 0.17677669529663687f;
    float lg[8];
    float m = -1e30f;
    for (int i = 0; i < nc; i++) {
        const float* kp = basep + (size_t)cand[i]*QKVW + 256;
        float dot = 0.0f;
#pragma unroll
        for (int j = 0; j < 8; j++) {
            float4 k4 = *(const float4*)(kp + j*4);
            dot += qr[j*4+0]*k4.x + qr[j*4+1]*k4.y + qr[j*4+2]*k4.z + qr[j*4+3]*k4.w;
        }
        lg[i] = dot * scale;
        m = fmaxf(m, lg[i]);
    }
    float ssum = 0.0f;
    float o[32];
#pragma unroll
    for (int d = 0; d < 32; d++) o[d] = 0.0f;
    for (int i = 0; i < nc; i++) {
        float p = __expf(lg[i] - m);
        ssum += p;
        const float* vp = basep + (size_t)cand[i]*QKVW + 512;
#pragma unroll
        for (int j = 0; j < 8; j++) {
            float4 v4 = *(const float4*)(vp + j*4);
            o[j*4+0] += p*v4.x; o[j*4+1] += p*v4.y; o[j*4+2] += p*v4.z; o[j*4+3] += p*v4.w;
        }
    }
    float inv = 1.0f / ssum;
#pragma unroll
    for (int j = 0; j < 8; j++) {
        float4 w4 = make_float4(rtf(o[j*4+0]*inv), rtf(o[j*4+1]*inv),
                                rtf(o[j*4+2]*inv), rtf(o[j*4+3]*inv));
        *(float4*)(op + j*4) = w4;
    }
}

__global__ void __launch_bounds__(256) bn_norm_kernel(
    const float* __restrict__ in, float* __restrict__ outp,
    const float* __restrict__ gamma, const float* __restrict__ beta,
    const float* __restrict__ sums, int out_ld)
{
    int tid = threadIdx.x;
    int f = (tid & 63)*4;
    int t = blockIdx.x*4 + (tid >> 6);
    float4 s  = *(const float4*)&sums[f];
    float4 s2 = *(const float4*)&sums[EE + f];
    const float invN = 1.0f/(float)TT;
    float m0 = s.x*invN, m1 = s.y*invN, m2 = s.z*invN, m3 = s.w*invN;
    float r0 = rsqrtf(s2.x*invN - m0*m0 + 1e-5f);
    float r1 = rsqrtf(s2.y*invN - m1*m1 + 1e-5f);
    float r2 = rsqrtf(s2.z*invN - m2*m2 + 1e-5f);
    float r3 = rsqrtf(s2.w*invN - m3*m3 + 1e-5f);
    float4 v  = *(const float4*)&in[(size_t)t*EE + f];
    float4 gm = *(const float4*)&gamma[f];
    float4 bt = *(const float4*)&beta[f];
    float4 o;
    o.x = rtf(gm.x*(v.x - m0)*r0 + bt.x);
    o.y = rtf(gm.y*(v.y - m1)*r1 + bt.y);
    o.z = rtf(gm.z*(v.z - m2)*r2 + bt.z);
    o.w = rtf(gm.w*(v.w - m3)*r3 + bt.w);
    *(float4*)&outp[(size_t)t*out_ld + f] = o;
}

__global__ void final_kernel(const float* __restrict__ mask, float* __restrict__ outp) {
    __shared__ float sM[SS];
    int b = blockIdx.x, e = threadIdx.x;
    sM[e] = mask[b*SS + e];
    __syncthreads();
    float acc = 0.0f;
    for (int s = 0; s < SS; s++) acc += g_xh[(size_t)(b*SS + s)*XHW + e]*sM[s];
    float denom = fmaxf((float)g_len[b], 1.0f);
    outp[b*EE + e] = acc/denom;
}

extern "C" void kernel_launch(void* const* d_in, const int* in_sizes, int n_in,
                              void* d_out, int out_size) {
    (void)in_sizes; (void)n_in; (void)out_size;
    const float* data = (const float*)d_in[0];
    const float* mask = (const float*)d_in[1];
    const float* Wc   = (const float*)d_in[2];
    const float* bc   = (const float*)d_in[3];
    const float* ftab = (const float*)d_in[4];
    const float* ptab = (const float*)d_in[5];
    const float* Wq   = (const float*)d_in[6];
    const float* Wk   = (const float*)d_in[7];
    const float* Wv   = (const float*)d_in[8];
    const float* Wo   = (const float*)d_in[9];
    const float* Wf   = (const float*)d_in[10];
    const float* bf   = (const float*)d_in[11];
    const float* g1   = (const float*)d_in[12];
    const float* b1   = (const float*)d_in[13];
    const float* Wff  = (const float*)d_in[14];
    const float* bff  = (const float*)d_in[15];
    const float* g2   = (const float*)d_in[16];
    const float* b2   = (const float*)d_in[17];
    float* outp = (float*)d_out;

    float *xh, *qkv, *h, *h2, *wqkv, *wf, *wff, *woR, *wcomb, *wbig, *sums;
    cudaGetSymbolAddress((void**)&xh,    g_xh);
    cudaGetSymbolAddress((void**)&qkv,   g_qkv);
    cudaGetSymbolAddress((void**)&h,     g_h);
    cudaGetSymbolAddress((void**)&h2,    g_h2);
    cudaGetSymbolAddress((void**)&wqkv,  g_wqkv);
    cudaGetSymbolAddress((void**)&wf,    g_wf);
    cudaGetSymbolAddress((void**)&wff,   g_wff);
    cudaGetSymbolAddress((void**)&woR,   g_woR);
    cudaGetSymbolAddress((void**)&wcomb, g_wcomb);
    cudaGetSymbolAddress((void**)&wbig,  g_wbig);
    cudaGetSymbolAddress((void**)&sums,  g_sums);

    cudaFuncSetAttribute(mma_gemm, cudaFuncAttributeMaxDynamicSharedMemorySize, GEMM_SMEM);

    pack_w<<<(12*HH*EE*DKK)/256, 256>>>(Wq, Wk, Wv);
    round_copy<<<(12*EE*EE)/256, 256>>>(Wo,  woR, 12*EE*EE);
    round_copy<<<(LL*E3*EE)/256, 256>>>(Wf,  wf,  LL*E3*EE);
    round_copy<<<(LL*EE*EE)/256, 256>>>(Wff, wff, LL*EE*EE);
    mma_gemm<<<dim3(2, 2, 12), 256, GEMM_SMEM>>>(
        woR, wf, wcomb, EE, EE, EE, EE, nullptr, nullptr, 0, 0,
        (size_t)EE*EE, (size_t)EE*EE, (size_t)EE*EE, nullptr);
    assemble_wbig<<<(LL*XHW*EE)/256, 256>>>(Wf);

    flags_kernel<<<BB, SS>>>(data, mask);
    embed_kernel<<<TT, EE>>>(data, Wc, bc, ftab, ptab);

    for (int l = 0; l < LL; l++) {
        mma_gemm<<<dim3(QKVW/128, TT/128, 1), 256, GEMM_SMEM>>>(
            xh, wqkv + (size_t)l*EE*QKVW, qkv,
            EE, XHW, QKVW, QKVW, nullptr, nullptr, 0, 0, 0, 0, 0, nullptr);
        attn_kernel<<<dim3(BB, HH, 3), 256>>>(qkv, xh);
        cudaMemsetAsync(sums, 0, 2*EE*sizeof(float), 0);
        mma_gemm<<<dim3(EE/128, TT/128, 1), 256, GEMM_SMEM>>>(
            xh, wbig + (size_t)l*XHW*EE, h,
            XHW, XHW, EE, EE, bf + l*EE, nullptr, 0, 0, 0, 0, 0, sums);
        bn_norm_kernel<<<TT/4, 256>>>(h, h, g1 + l*EE, b1 + l*EE, sums, EE);
        cudaMemsetAsync(sums, 0, 2*EE*sizeof(float), 0);
        mma_gemm<<<dim3(EE/128, TT/128, 1), 256, GEMM_SMEM>>>(
            h, wff + (size_t)l*EE*EE, h2,
            EE, EE, EE, EE, bff + l*EE, h, EE, 1, 0, 0, 0, sums);
        bn_norm_kernel<<<TT/4, 256>>>(h2, xh, g2 + l*EE, b2 + l*EE, sums, XHW);
    }
    final_kernel<<<BB, EE>>>(mask, outp);
}

// round 14
// speedup vs baseline: 5.8797x; 1.1006x over previous
#include <cuda_runtime.h>

#define BB 32
#define SS 256
#define EE 256
#define HH 8
#define DKK 32
#define LL 4
#define TT (BB*SS)
#define E3 (3*EE)
#define QKVW 2304
#define XHW 1024

__device__ float g_xh[TT*XHW];
__device__ float g_qkv[TT*QKVW];
__device__ float g_h[TT*EE];
__device__ float g_h2[TT*EE];
__device__ float g_wqkvT[LL*QKVW*EE];   // [l][c][e]  (transposed, tf32-rounded)
__device__ float g_wfT[12*EE*EE];       // [z][n][j]
__device__ float g_wffT[LL*EE*EE];      // [l][n][k]
__device__ float g_woR[12*EE*EE];       // [z][d][j] rounded
__device__ float g_wcomb[12*EE*EE];     // [z][d][n]
__device__ float g_wbigT[LL*EE*XHW];    // [l][n][r]
__device__ int   g_flag[TT];
__device__ int   g_len[BB];
__device__ float g_sums[4*EE];          // [0,512)=sums_a, [512,1024)=sums_b

__device__ __forceinline__ unsigned f2tf(float x) {
    unsigned r; asm("cvt.rna.tf32.f32 %0, %1;" : "=r"(r) : "f"(x)); return r;
}
__device__ __forceinline__ float rtf(float x) { return __uint_as_float(f2tf(x)); }

// ---- merged weight prep: pack qkv(T) + round Wo + wfT + wffT ----
#define N_PACK (12*HH*EE*DKK)           // 786432
__global__ void prep_w(const float* __restrict__ Wq, const float* __restrict__ Wk,
                       const float* __restrict__ Wv, const float* __restrict__ Wo,
                       const float* __restrict__ Wf, const float* __restrict__ Wff) {
    int id = blockIdx.x*blockDim.x + threadIdx.x;
    if (id < N_PACK) {
        int d  = id % DKK;
        int e  = (id / DKK) % EE;
        int h  = (id / (DKK*EE)) % HH;
        int lg = id / (DKK*EE*HH);
        int l = lg / 3, g = lg % 3;
        int col = g*768 + h*DKK + d;
        size_t base = (size_t)l*QKVW*EE;
        g_wqkvT[base + (size_t)(col +   0)*EE + e] = rtf(Wq[id]);
        g_wqkvT[base + (size_t)(col + 256)*EE + e] = rtf(Wk[id]);
        g_wqkvT[base + (size_t)(col + 512)*EE + e] = rtf(Wv[id]);
    } else if (id < 2*N_PACK) {
        int i = id - N_PACK;
        g_woR[i] = rtf(Wo[i]);
    } else if (id < 3*N_PACK) {
        int i = id - 2*N_PACK;
        int j = i % EE, n = (i/EE) % EE, z = i/(EE*EE);
        int l = z/3, g = z%3;
        g_wfT[i] = rtf(Wf[(size_t)l*E3*EE + (size_t)(g*256+j)*EE + n]);
    } else {
        int i = id - 3*N_PACK;           // LL*EE*EE
        int k = i % EE, n = (i/EE) % EE, l = i/(EE*EE);
        g_wffT[i] = rtf(Wff[(size_t)l*EE*EE + (size_t)k*EE + n]);
    }
}
__global__ void assemble_wbigT(const float* __restrict__ Wf) {
    int id = blockIdx.x*blockDim.x + threadIdx.x;   // LL*EE*XHW
    int r = id % XHW, n = (id/XHW) % EE, l = id/(XHW*EE);
    float v;
    if (r < 256) {
        const float* wf = Wf + (size_t)l*E3*EE;
        v = wf[(size_t)r*EE+n] + wf[(size_t)(256+r)*EE+n] + wf[(size_t)(512+r)*EE+n];
    } else {
        int g = (r-256) >> 8, d = (r-256) & 255;
        v = g_wcomb[(size_t)(l*3+g)*EE*EE + (size_t)d*EE + n];
    }
    g_wbigT[id] = rtf(v);
}

__global__ void flags_kernel(const float* __restrict__ data, const float* __restrict__ mask) {
    int b = blockIdx.x, s = threadIdx.x;
    int idx = b*SS + s;
    float mk = mask[idx];
    float p1 = data[idx*5+2], p2 = data[idx*5+3], p3 = data[idx*5+4];
    int f = 0;
    if (p1 == 1.0f) f = 100;
    if (p2 == 1.0f || p3 == 1.0f) f = 101;
    if (mk == 0.0f) f = 102;
    g_flag[idx] = f;
    __shared__ float red[SS];
    red[s] = mk;
    __syncthreads();
    for (int st = 128; st > 0; st >>= 1) {
        if (s < st) red[s] += red[s+st];
        __syncthreads();
    }
    if (s == 0) g_len[b] = (int)(red[0] + 0.5f);
}

__global__ void embed_kernel(const float* __restrict__ data, const float* __restrict__ Wc,
                             const float* __restrict__ bc, const float* __restrict__ ftab,
                             const float* __restrict__ ptab) {
    int t = blockIdx.x, e = threadIdx.x;
    float c0 = data[t*5+0], c1 = data[t*5+1];
    int fl = g_flag[t];
    int s = t & (SS-1);
    g_xh[(size_t)t*XHW + e] = rtf(c0*Wc[e] + c1*Wc[EE+e] + bc[e] + ftab[fl*EE+e] + ptab[s*EE+e]);
}

// ---- tf32 mma.sync GEMM, B transposed [n][k], ldmatrix fragment loads ----
__device__ __forceinline__ void cpasync16(float* dst, const float* src) {
    unsigned s = (unsigned)__cvta_generic_to_shared(dst);
    asm volatile("cp.async.cg.shared.global [%0], [%1], 16;" :: "r"(s), "l"(src));
}
#define TILE_ST 36
#define TILE_W (128*TILE_ST)            // 4608 words per operand tile
#define BUF_W (2*TILE_W)                // 9216 words
#define GEMM_SMEM (2*BUF_W*4)           // 73728 B; 2 CTAs/SM

// stage A rows m0.. and BT rows n0..: both 128 rows x 32 k
__device__ __forceinline__ void load_tile(float* bufA, float* bufB,
        const float* A, const float* BT, int lda, int ldb,
        int m0, int n0, int k0, int tid)
{
    int row = tid >> 1, c = (tid & 1)*16;
    {
        const float* src = A + (size_t)(m0 + row)*lda + k0 + c;
        float* dst = bufA + row*TILE_ST + c;
        cpasync16(dst, src);      cpasync16(dst + 4,  src + 4);
        cpasync16(dst + 8, src+8); cpasync16(dst + 12, src + 12);
    }
    {
        const float* src = BT + (size_t)(n0 + row)*ldb + k0 + c;
        float* dst = bufB + row*TILE_ST + c;
        cpasync16(dst, src);      cpasync16(dst + 4,  src + 4);
        cpasync16(dst + 8, src+8); cpasync16(dst + 12, src + 12);
    }
    asm volatile("cp.async.commit_group;");
}

__global__ void __launch_bounds__(256, 2) mma_gemm(
    const float* __restrict__ A, const float* __restrict__ BT, float* __restrict__ C,
    int K, int lda, int ldb, int ldc,
    const float* __restrict__ bias, const float* __restrict__ resid, int ldr, int relu,
    size_t batchA, size_t batchB, size_t batchC, float* stats)
{
    extern __shared__ float smem[];
    int z = blockIdx.z;
    A  += (size_t)z*batchA; BT += (size_t)z*batchB; C += (size_t)z*batchC;
    int tid = threadIdx.x, lane = tid & 31, warp = tid >> 5;
    int wm = warp & 1, wn = warp >> 1;
    int m0 = blockIdx.y*128, n0 = blockIdx.x*128;
    float acc[4][4][4];
#pragma unroll
    for (int a2 = 0; a2 < 4; a2++)
#pragma unroll
        for (int b2 = 0; b2 < 4; b2++)
#pragma unroll
            for (int c2 = 0; c2 < 4; c2++) acc[a2][b2][c2] = 0.0f;

    unsigned sbase = (unsigned)__cvta_generic_to_shared(smem);
    // ldmatrix per-lane address offsets (bytes), within a buffer
    unsigned aoff = ((unsigned)((wm*64 + (lane & 15))*TILE_ST) + (lane >= 16 ? 4u : 0u))*4u;
    unsigned boff = (unsigned)TILE_W*4u +
                    ((unsigned)((wn*32 + (lane & 7) + ((lane >> 4) << 3))*TILE_ST) +
                     ((lane >> 3) & 1)*4u)*4u;

    int nk = K >> 5;
    load_tile(smem, smem + TILE_W, A, BT, lda, ldb, m0, n0, 0, tid);

    for (int it = 0; it < nk; it++) {
        asm volatile("cp.async.wait_group 0;");
        __syncthreads();
        int cur = it & 1;
        if (it + 1 < nk)
            load_tile(smem + (cur^1)*BUF_W, smem + (cur^1)*BUF_W + TILE_W,
                      A, BT, lda, ldb, m0, n0, (it+1)*32, tid);
        unsigned ubuf = sbase + (unsigned)cur*BUF_W*4u;
#pragma unroll
        for (int kk = 0; kk < 4; kk++) {
            unsigned kbb = (unsigned)(kk*8)*4u;
            unsigned af[4][4], bf[4][2];
#pragma unroll
            for (int mt = 0; mt < 4; mt++) {
                unsigned addr = ubuf + aoff + (unsigned)(mt*16*TILE_ST)*4u + kbb;
                asm volatile("ldmatrix.sync.aligned.m8n8.x4.shared.b16 {%0,%1,%2,%3}, [%4];"
                    : "=r"(af[mt][0]), "=r"(af[mt][1]), "=r"(af[mt][2]), "=r"(af[mt][3])
                    : "r"(addr));
            }
#pragma unroll
            for (int p = 0; p < 2; p++) {
                unsigned addr = ubuf + boff + (unsigned)(p*16*TILE_ST)*4u + kbb;
                asm volatile("ldmatrix.sync.aligned.m8n8.x4.shared.b16 {%0,%1,%2,%3}, [%4];"
                    : "=r"(bf[2*p][0]), "=r"(bf[2*p][1]), "=r"(bf[2*p+1][0]), "=r"(bf[2*p+1][1])
                    : "r"(addr));
            }
#pragma unroll
            for (int mt = 0; mt < 4; mt++)
#pragma unroll
                for (int nt = 0; nt < 4; nt++)
                    asm volatile(
                        "mma.sync.aligned.m16n8k8.row.col.f32.tf32.tf32.f32 "
                        "{%0,%1,%2,%3}, {%4,%5,%6,%7}, {%8,%9}, {%0,%1,%2,%3};"
                        : "+f"(acc[mt][nt][0]), "+f"(acc[mt][nt][1]),
                          "+f"(acc[mt][nt][2]), "+f"(acc[mt][nt][3])
                        : "r"(af[mt][0]), "r"(af[mt][1]), "r"(af[mt][2]), "r"(af[mt][3]),
                          "r"(bf[nt][0]), "r"(bf[nt][1]));
        }
    }
    float cs[4][2] = {}, cs2[4][2] = {};
#pragma unroll
    for (int mt = 0; mt < 4; mt++) {
#pragma unroll
        for (int nt = 0; nt < 4; nt++) {
            int r = m0 + wm*64 + mt*16 + (lane >> 2);
            int c = n0 + wn*32 + nt*8 + (lane & 3)*2;
#pragma unroll
            for (int half = 0; half < 2; half++) {
                int rr = r + half*8;
                float v0 = acc[mt][nt][half*2+0];
                float v1 = acc[mt][nt][half*2+1];
                if (bias)  { v0 += bias[c];  v1 += bias[c+1]; }
                if (relu)  { v0 = fmaxf(v0, 0.0f); v1 = fmaxf(v1, 0.0f); }
                if (resid) {
                    float2 rv = *(const float2*)&resid[(size_t)rr*ldr + c];
                    v0 += rv.x; v1 += rv.y;
                }
                *(float2*)&C[(size_t)rr*ldc + c] = make_float2(v0, v1);
                if (stats) {
                    cs[nt][0]  += v0;    cs[nt][1]  += v1;
                    cs2[nt][0] += v0*v0; cs2[nt][1] += v1*v1;
                }
            }
        }
    }
    if (stats) {
        float* red = smem;
        __syncthreads();
        if (tid < 256) red[tid] = 0.0f;
        __syncthreads();
#pragma unroll
        for (int nt = 0; nt < 4; nt++) {
#pragma unroll
            for (int j = 0; j < 2; j++) {
                float s = cs[nt][j], s2 = cs2[nt][j];
#pragma unroll
                for (int o = 16; o >= 4; o >>= 1) {
                    s  += __shfl_xor_sync(0xffffffffu, s,  o);
                    s2 += __shfl_xor_sync(0xffffffffu, s2, o);
                }
                if ((lane >> 2) == 0) {
                    int cc = wn*32 + nt*8 + (lane & 3)*2 + j;
                    atomicAdd(&red[cc], s);
                    atomicAdd(&red[128 + cc], s2);
                }
            }
        }
        __syncthreads();
        if (tid < 128) {
            atomicAdd(&stats[n0 + tid],      red[tid]);
            atomicAdd(&stats[EE + n0 + tid], red[128 + tid]);
        }
    }
}

__device__ __forceinline__ bool adj_fn(int g, int q, int k, int len, const int* fl) {
    if (q == k) return q < len;
    if (g == 0) {
        if (k == q+1) return fl[q] == 100 && q < len-1;
        if (q == k+1) return fl[k] == 100 && k < len-1;
        return false;
    } else if (g == 1) {
        if (k == q+1) return fl[q] == 100 && q < len-1;
        if (q == k+1) return fl[k] == 100 && k < len-1;
        if (k == q+2) return fl[q] == 100 && fl[q+1] == 100 && q < len-2;
        if (q == k+2) return fl[k] == 100 && fl[k+1] == 100 && k < len-2;
        return false;
    } else {
        if (q == 0 && k == len-1 && len > 1) return true;
        if (k == 0 && q == len-1 && len > 1) return true;
        if (k == q+1) return fl[q] == 101 && q < len-1;
        if (q == k+1) return fl[k] == 101 && k < len-1;
        return false;
    }
}

__global__ void __launch_bounds__(256) attn_kernel(
    const float* __restrict__ qkv, float* __restrict__ xh)
{
    __shared__ float sPart[8][32];
    __shared__ float sVmean[32];
    __shared__ int   sFlag[SS];
    __shared__ int   sLenS;
    int b = blockIdx.x, h = blockIdx.y, g = blockIdx.z;
    int tid = threadIdx.x;
    if (b == 0 && h == 0 && g == 0) {           // zero BN-stat accumulators for this layer
        g_sums[tid] = 0.0f; g_sums[256+tid] = 0.0f;
        g_sums[512+tid] = 0.0f; g_sums[768+tid] = 0.0f;
    }
    const float* basep = qkv + (size_t)b*SS*QKVW + g*768 + h*DKK;
    {
        int d = tid & 31, ch = tid >> 5;
        float s = 0.0f;
        for (int r = ch*32; r < ch*32 + 32; r++)
            s += basep[(size_t)r*QKVW + 512 + d];
        sPart[ch][d] = s;
    }
    sFlag[tid] = g_flag[b*SS + tid];
    if (tid == 0) sLenS = g_len[b];
    __syncthreads();
    if (tid < 32) {
        float s = 0.0f;
#pragma unroll
        for (int c2 = 0; c2 < 8; c2++) s += sPart[c2][tid];
        sVmean[tid] = rtf(s * (1.0f/256.0f));
    }
    __syncthreads();
    int qi = tid, len = sLenS;
    float* op = xh + (size_t)(b*SS + qi)*XHW + 256 + g*256 + h*DKK;
    if (qi >= len) {
#pragma unroll
        for (int j = 0; j < 8; j++)
            *(float4*)(op + j*4) = *(float4*)(&sVmean[j*4]);
        return;
    }
    float qr[32];
    const float* qp = basep + (size_t)qi*QKVW;
#pragma unroll
    for (int j = 0; j < 8; j++) {
        float4 t4 = *(const float4*)(qp + j*4);
        qr[j*4+0] = t4.x; qr[j*4+1] = t4.y; qr[j*4+2] = t4.z; qr[j*4+3] = t4.w;
    }
    int cand[8]; int nc = 0;
    int pot[7];  int np = 0;
    if (g == 2) pot[np++] = 0;
    pot[np++] = qi-2; pot[np++] = qi-1; pot[np++] = qi; pot[np++] = qi+1; pot[np++] = qi+2;
    if (g == 2) pot[np++] = len-1;
    for (int i = 0; i < np; i++) {
        int kk = pot[i];
        if (kk < 0 || kk >= SS) continue;
        if (!adj_fn(g, qi, kk, len, sFlag)) continue;
        bool dup = false;
        for (int u = 0; u < nc; u++) if (cand[u] == kk) dup = true;
        if (!dup) cand[nc++] = kk;
    }
    const float scale = 0.17677669529663687f;
    float lg[8];
    float m = -1e30f;
    for (int i = 0; i < nc; i++) {
        const float* kp = basep + (size_t)cand[i]*QKVW + 256;
        float dot = 0.0f;
#pragma unroll
        for (int j = 0; j < 8; j++) {
            float4 k4 = *(const float4*)(kp + j*4);
            dot += qr[j*4+0]*k4.x + qr[j*4+1]*k4.y + qr[j*4+2]*k4.z + qr[j*4+3]*k4.w;
        }
        lg[i] = dot * scale;
        m = fmaxf(m, lg[i]);
    }
    float ssum = 0.0f;
    float o[32];
#pragma unroll
    for (int d = 0; d < 32; d++) o[d] = 0.0f;
    for (int i = 0; i < nc; i++) {
        float p = __expf(lg[i] - m);
        ssum += p;
        const float* vp = basep + (size_t)cand[i]*QKVW + 512;
#pragma unroll
        for (int j = 0; j < 8; j++) {
            float4 v4 = *(const float4*)(vp + j*4);
            o[j*4+0] += p*v4.x; o[j*4+1] += p*v4.y; o[j*4+2] += p*v4.z; o[j*4+3] += p*v4.w;
        }
    }
    float inv = 1.0f / ssum;
#pragma unroll
    for (int j = 0; j < 8; j++) {
        float4 w4 = make_float4(rtf(o[j*4+0]*inv), rtf(o[j*4+1]*inv),
                                rtf(o[j*4+2]*inv), rtf(o[j*4+3]*inv));
        *(float4*)(op + j*4) = w4;
    }
}

__global__ void __launch_bounds__(256) bn_norm_kernel(
    const float* __restrict__ in, float* __restrict__ outp,
    const float* __restrict__ gamma, const float* __restrict__ beta,
    const float* __restrict__ sums, int out_ld)
{
    int tid = threadIdx.x;
    int f = (tid & 63)*4;
    int t = blockIdx.x*4 + (tid >> 6);
    float4 s  = *(const float4*)&sums[f];
    float4 s2 = *(const float4*)&sums[EE + f];
    const float invN = 1.0f/(float)TT;
    float m0 = s.x*invN, m1 = s.y*invN, m2 = s.z*invN, m3 = s.w*invN;
    float r0 = rsqrtf(s2.x*invN - m0*m0 + 1e-5f);
    float r1 = rsqrtf(s2.y*invN - m1*m1 + 1e-5f);
    float r2 = rsqrtf(s2.z*invN - m2*m2 + 1e-5f);
    float r3 = rsqrtf(s2.w*invN - m3*m3 + 1e-5f);
    float4 v  = *(const float4*)&in[(size_t)t*EE + f];
    float4 gm = *(const float4*)&gamma[f];
    float4 bt = *(const float4*)&beta[f];
    float4 o;
    o.x = rtf(gm.x*(v.x - m0)*r0 + bt.x);
    o.y = rtf(gm.y*(v.y - m1)*r1 + bt.y);
    o.z = rtf(gm.z*(v.z - m2)*r2 + bt.z);
    o.w = rtf(gm.w*(v.w - m3)*r3 + bt.w);
    *(float4*)&outp[(size_t)t*out_ld + f] = o;
}

__global__ void final_kernel(const float* __restrict__ mask, float* __restrict__ outp) {
    __shared__ float sM[SS];
    int b = blockIdx.x, e = threadIdx.x;
    sM[e] = mask[b*SS + e];
    __syncthreads();
    float acc = 0.0f;
    for (int s = 0; s < SS; s++) acc += g_xh[(size_t)(b*SS + s)*XHW + e]*sM[s];
    float denom = fmaxf((float)g_len[b], 1.0f);
    outp[b*EE + e] = acc/denom;
}

extern "C" void kernel_launch(void* const* d_in, const int* in_sizes, int n_in,
                              void* d_out, int out_size) {
    (void)in_sizes; (void)n_in; (void)out_size;
    const float* data = (const float*)d_in[0];
    const float* mask = (const float*)d_in[1];
    const float* Wc   = (const float*)d_in[2];
    const float* bc   = (const float*)d_in[3];
    const float* ftab = (const float*)d_in[4];
    const float* ptab = (const float*)d_in[5];
    const float* Wq   = (const float*)d_in[6];
    const float* Wk   = (const float*)d_in[7];
    const float* Wv   = (const float*)d_in[8];
    const float* Wo   = (const float*)d_in[9];
    const float* Wf   = (const float*)d_in[10];
    const float* bf   = (const float*)d_in[11];
    const float* g1   = (const float*)d_in[12];
    const float* b1   = (const float*)d_in[13];
    const float* Wff  = (const float*)d_in[14];
    const float* bff  = (const float*)d_in[15];
    const float* g2   = (const float*)d_in[16];
    const float* b2   = (const float*)d_in[17];
    float* outp = (float*)d_out;

    float *xh, *qkv, *h, *h2, *wqkvT, *wfT, *wffT, *woR, *wcomb, *wbigT, *sums;
    cudaGetSymbolAddress((void**)&xh,    g_xh);
    cudaGetSymbolAddress((void**)&qkv,   g_qkv);
    cudaGetSymbolAddress((void**)&h,     g_h);
    cudaGetSymbolAddress((void**)&h2,    g_h2);
    cudaGetSymbolAddress((void**)&wqkvT, g_wqkvT);
    cudaGetSymbolAddress((void**)&wfT,   g_wfT);
    cudaGetSymbolAddress((void**)&wffT,  g_wffT);
    cudaGetSymbolAddress((void**)&woR,   g_woR);
    cudaGetSymbolAddress((void**)&wcomb, g_wcomb);
    cudaGetSymbolAddress((void**)&wbigT, g_wbigT);
    cudaGetSymbolAddress((void**)&sums,  g_sums);

    cudaFuncSetAttribute(mma_gemm, cudaFuncAttributeMaxDynamicSharedMemorySize, GEMM_SMEM);

    prep_w<<<(3*N_PACK + LL*EE*EE)/256, 256>>>(Wq, Wk, Wv, Wo, Wf, Wff);
    // wcomb[z][d][n] = sum_j woR[z][d][j] * wfT[z][n][j]
    mma_gemm<<<dim3(2, 2, 12), 256, GEMM_SMEM>>>(
        woR, wfT, wcomb, EE, EE, EE, EE, nullptr, nullptr, 0, 0,
        (size_t)EE*EE, (size_t)EE*EE, (size_t)EE*EE, nullptr);
    assemble_wbigT<<<(LL*EE*XHW)/256, 256>>>(Wf);

    flags_kernel<<<BB, SS>>>(data, mask);
    embed_kernel<<<TT, EE>>>(data, Wc, bc, ftab, ptab);

    for (int l = 0; l < LL; l++) {
        // qkv[t][c] = sum_e xh[t][e] * wqkvT[l][c][e]
        mma_gemm<<<dim3(QKVW/128, TT/128, 1), 256, GEMM_SMEM>>>(
            xh, wqkvT + (size_t)l*QKVW*EE, qkv,
            EE, XHW, EE, QKVW, nullptr, nullptr, 0, 0, 0, 0, 0, nullptr);
        attn_kernel<<<dim3(BB, HH, 3), 256>>>(qkv, xh);   // also zeroes g_sums
        // h[t][n] = sum_r xh[t][r] * wbigT[l][n][r] + bf  (stats -> sums_a)
        mma_gemm<<<dim3(EE/128, TT/128, 1), 256, GEMM_SMEM>>>(
            xh, wbigT + (size_t)l*EE*XHW, h,
            XHW, XHW, XHW, EE, bf + l*EE, nullptr, 0, 0, 0, 0, 0, sums);
        bn_norm_kernel<<<TT/4, 256>>>(h, h, g1 + l*EE, b1 + l*EE, sums, EE);
        // h2 = h + relu(h @ Wff + bff)  (stats -> sums_b)
        mma_gemm<<<dim3(EE/128, TT/128, 1), 256, GEMM_SMEM>>>(
            h, wffT + (size_t)l*EE*EE, h2,
            EE, EE, EE, EE, bff + l*EE, h, EE, 1, 0, 0, 0, sums + 2*EE);
        bn_norm_kernel<<<TT/4, 256>>>(h2, xh, g2 + l*EE, b2 + l*EE, sums + 2*EE, XHW);
    }
    final_kernel<<<BB, EE>>>(mask, outp);
}